// round 4
// baseline (speedup 1.0000x reference)
#include <cuda_runtime.h>
#include <math.h>

#define BB 4
#define NN 2048
#define NF 256
#define NH 8
#define DD 64
#define C1 512   // NH*DD
#define NO 128

#define TI 16
#define TJ 32

// Scratch (device globals -- no allocations allowed)
__device__ float  g_h1[BB*NN*C1];     // layer1 linear output
__device__ float  g_z1[BB*NN*C1];     // layer1 attention output (= hcat)
__device__ float  g_h2[BB*NN*NO];     // layer2 linear output
__device__ float2 g_ef1[BB*NN*NH];    // (exp(s1), exp(0.1 s1)) per (b,n,head)
__device__ float2 g_ef2[BB*NN*NH];    // (exp(s2), exp(0.1 s2))
__device__ float2 g_ef1o[BB*NN];      // layer2 versions
__device__ float2 g_ef2o[BB*NN];

// ---------------------------------------------------------------------------
// GEMM1: g_h1[m][c] = sum_k X[m][k] * Wh[c/64][k][c%64],  M=8192,K=256,Ncol=512
// 64x64 tiles, BK=16, 256 threads, 4x4 per thread.
// ---------------------------------------------------------------------------
__global__ __launch_bounds__(256) void gemm1_kernel(const float* __restrict__ X,
                                                    const float* __restrict__ Wh) {
    __shared__ float As[16][68];
    __shared__ float Bs[16][68];
    const int tid = threadIdx.x;
    const int tx = tid & 15, ty = tid >> 4;
    const int n0 = blockIdx.x * 64;       // column tile (head-aligned: 64 cols)
    const int m0 = blockIdx.y * 64;       // row tile
    const int head = n0 >> 6;

    const int arow = tid >> 2, akq = tid & 3;   // A loader
    const int brow = tid >> 4, bn4 = tid & 15;  // B loader

    float acc[4][4] = {};

    for (int kk = 0; kk < NF; kk += 16) {
        float4 av = *(const float4*)&X[(size_t)(m0 + arow) * NF + kk + akq * 4];
        As[akq*4+0][arow] = av.x; As[akq*4+1][arow] = av.y;
        As[akq*4+2][arow] = av.z; As[akq*4+3][arow] = av.w;
        float4 bv = *(const float4*)&Wh[(size_t)head*(NF*DD) + (size_t)(kk + brow)*DD + bn4*4];
        *(float4*)&Bs[brow][bn4*4] = bv;
        __syncthreads();
        #pragma unroll
        for (int k = 0; k < 16; ++k) {
            float a0 = As[k][ty*4+0], a1 = As[k][ty*4+1];
            float a2 = As[k][ty*4+2], a3 = As[k][ty*4+3];
            float4 b = *(float4*)&Bs[k][tx*4];
            acc[0][0] = fmaf(a0, b.x, acc[0][0]); acc[0][1] = fmaf(a0, b.y, acc[0][1]);
            acc[0][2] = fmaf(a0, b.z, acc[0][2]); acc[0][3] = fmaf(a0, b.w, acc[0][3]);
            acc[1][0] = fmaf(a1, b.x, acc[1][0]); acc[1][1] = fmaf(a1, b.y, acc[1][1]);
            acc[1][2] = fmaf(a1, b.z, acc[1][2]); acc[1][3] = fmaf(a1, b.w, acc[1][3]);
            acc[2][0] = fmaf(a2, b.x, acc[2][0]); acc[2][1] = fmaf(a2, b.y, acc[2][1]);
            acc[2][2] = fmaf(a2, b.z, acc[2][2]); acc[2][3] = fmaf(a2, b.w, acc[2][3]);
            acc[3][0] = fmaf(a3, b.x, acc[3][0]); acc[3][1] = fmaf(a3, b.y, acc[3][1]);
            acc[3][2] = fmaf(a3, b.z, acc[3][2]); acc[3][3] = fmaf(a3, b.w, acc[3][3]);
        }
        __syncthreads();
    }
    #pragma unroll
    for (int u = 0; u < 4; ++u) {
        float4 v = make_float4(acc[u][0], acc[u][1], acc[u][2], acc[u][3]);
        *(float4*)&g_h1[(size_t)(m0 + ty*4 + u) * C1 + n0 + tx*4] = v;
    }
}

// ---------------------------------------------------------------------------
// GEMM2: g_h2 = g_z1 @ Wo,  M=8192, K=512, Ncol=128
// ---------------------------------------------------------------------------
__global__ __launch_bounds__(256) void gemm2_kernel(const float* __restrict__ Wo) {
    __shared__ float As[16][68];
    __shared__ float Bs[16][68];
    const int tid = threadIdx.x;
    const int tx = tid & 15, ty = tid >> 4;
    const int n0 = blockIdx.x * 64;
    const int m0 = blockIdx.y * 64;

    const int arow = tid >> 2, akq = tid & 3;
    const int brow = tid >> 4, bn4 = tid & 15;

    float acc[4][4] = {};

    for (int kk = 0; kk < C1; kk += 16) {
        float4 av = *(const float4*)&g_z1[(size_t)(m0 + arow) * C1 + kk + akq * 4];
        As[akq*4+0][arow] = av.x; As[akq*4+1][arow] = av.y;
        As[akq*4+2][arow] = av.z; As[akq*4+3][arow] = av.w;
        float4 bv = *(const float4*)&Wo[(size_t)(kk + brow) * NO + n0 + bn4*4];
        *(float4*)&Bs[brow][bn4*4] = bv;
        __syncthreads();
        #pragma unroll
        for (int k = 0; k < 16; ++k) {
            float a0 = As[k][ty*4+0], a1 = As[k][ty*4+1];
            float a2 = As[k][ty*4+2], a3 = As[k][ty*4+3];
            float4 b = *(float4*)&Bs[k][tx*4];
            acc[0][0] = fmaf(a0, b.x, acc[0][0]); acc[0][1] = fmaf(a0, b.y, acc[0][1]);
            acc[0][2] = fmaf(a0, b.z, acc[0][2]); acc[0][3] = fmaf(a0, b.w, acc[0][3]);
            acc[1][0] = fmaf(a1, b.x, acc[1][0]); acc[1][1] = fmaf(a1, b.y, acc[1][1]);
            acc[1][2] = fmaf(a1, b.z, acc[1][2]); acc[1][3] = fmaf(a1, b.w, acc[1][3]);
            acc[2][0] = fmaf(a2, b.x, acc[2][0]); acc[2][1] = fmaf(a2, b.y, acc[2][1]);
            acc[2][2] = fmaf(a2, b.z, acc[2][2]); acc[2][3] = fmaf(a2, b.w, acc[2][3]);
            acc[3][0] = fmaf(a3, b.x, acc[3][0]); acc[3][1] = fmaf(a3, b.y, acc[3][1]);
            acc[3][2] = fmaf(a3, b.z, acc[3][2]); acc[3][3] = fmaf(a3, b.w, acc[3][3]);
        }
        __syncthreads();
    }
    #pragma unroll
    for (int u = 0; u < 4; ++u) {
        float4 v = make_float4(acc[u][0], acc[u][1], acc[u][2], acc[u][3]);
        *(float4*)&g_h2[(size_t)(m0 + ty*4 + u) * NO + n0 + tx*4] = v;
    }
}

// ---------------------------------------------------------------------------
// Scores layer1: per (b,n,head): s1 = h.a1, s2 = h.a2, store exp coefficients
// grid (NN, BB), 256 threads (warp w handles head w)
// ---------------------------------------------------------------------------
__global__ __launch_bounds__(256) void scores1_kernel(const float* __restrict__ ah) {
    const int n = blockIdx.x, b = blockIdx.y;
    const int w = threadIdx.x >> 5, lane = threadIdx.x & 31;
    const size_t row = (size_t)b * NN + n;
    const float* hrow = &g_h1[row * C1 + w * DD];
    float v0 = hrow[lane], v1 = hrow[lane + 32];
    const float* a = &ah[w * 2 * DD];
    float s1 = v0 * a[lane] + v1 * a[lane + 32];
    float s2 = v0 * a[DD + lane] + v1 * a[DD + lane + 32];
    #pragma unroll
    for (int s = 16; s; s >>= 1) {
        s1 += __shfl_down_sync(0xFFFFFFFFu, s1, s);
        s2 += __shfl_down_sync(0xFFFFFFFFu, s2, s);
    }
    if (lane == 0) {
        g_ef1[row * NH + w] = make_float2(expf(s1), expf(0.1f * s1));
        g_ef2[row * NH + w] = make_float2(expf(s2), expf(0.1f * s2));
    }
}

// ---------------------------------------------------------------------------
// Scores layer2: single head over 128 features. grid (NN, BB), 128 threads.
// ---------------------------------------------------------------------------
__global__ __launch_bounds__(128) void scores2_kernel(const float* __restrict__ ao) {
    __shared__ float s1s[128], s2s[128];
    const int n = blockIdx.x, b = blockIdx.y;
    const size_t row = (size_t)b * NN + n;
    const int t = threadIdx.x;
    float v = g_h2[row * NO + t];
    s1s[t] = v * ao[t];
    s2s[t] = v * ao[NO + t];
    __syncthreads();
    for (int s = 64; s; s >>= 1) {
        if (t < s) { s1s[t] += s1s[t + s]; s2s[t] += s2s[t + s]; }
        __syncthreads();
    }
    if (t == 0) {
        float s1 = s1s[0], s2 = s2s[0];
        g_ef1o[row] = make_float2(expf(s1), expf(0.1f * s1));
        g_ef2o[row] = make_float2(expf(s2), expf(0.1f * s2));
    }
}

// ---------------------------------------------------------------------------
// Aggregation layer1 (fused masked-softmax + weighted sum + bias + ELU).
// Block: (b, 16-row tile). 256 threads = 8 warps; warp w owns head w,
// lane owns cols 64w+lane and 64w+lane+32. Denominator accumulated inline,
// normalization deferred to epilogue.
// Dynamic smem layout: h-tile[TJ][C1] | w-tile[NH][TI][TJ] | ef1 | ef2 | l
// ---------------------------------------------------------------------------
__global__ __launch_bounds__(256, 2) void agg1_kernel(const int* __restrict__ adj,
                                                      const float* __restrict__ bh) {
    extern __shared__ float sm[];
    float (*sh_h)[C1] = (float(*)[C1])sm;                               // 16384 f
    float (*sh_w)[TI][TJ] = (float(*)[TI][TJ])(sm + TJ * C1);           // 4096 f
    float2* sh_ef1 = (float2*)(sm + TJ * C1 + NH * TI * TJ);            // 128 f2
    float2* sh_ef2 = sh_ef1 + TI * NH;                                  // 256 f2
    float*  sh_l   = (float*)(sh_ef2 + TJ * NH);                        // 128 f

    const int tid = threadIdx.x;
    const int b = blockIdx.y;
    const int i0 = blockIdx.x * TI;
    const int warp = tid >> 5, lane = tid & 31;
    const int head = warp;
    const int c0 = head * DD + lane, c1 = c0 + 32;
    const int wjl = tid & 31, wil = tid >> 5;   // weight-phase (j,i) mapping

    if (tid < TI * NH)
        sh_ef1[tid] = g_ef1[((size_t)b * NN + i0 + (tid >> 3)) * NH + (tid & 7)];

    float lacc[2][NH];
    #pragma unroll
    for (int p = 0; p < 2; ++p)
        #pragma unroll
        for (int h = 0; h < NH; ++h) lacc[p][h] = 0.0f;
    float acc0[TI], acc1[TI];
    #pragma unroll
    for (int i = 0; i < TI; ++i) { acc0[i] = 0.0f; acc1[i] = 0.0f; }

    for (int j0 = 0; j0 < NN; j0 += TJ) {
        __syncthreads();
        // stage ef2 for this j-tile (tid -> (j = tid>>3, h = tid&7))
        sh_ef2[tid] = g_ef2[((size_t)b * NN + j0 + (tid >> 3)) * NH + (tid & 7)];
        // load h tile (32 x 512 floats, float4)
        #pragma unroll
        for (int r = 0; r < 16; ++r) {
            int idx = r * 256 + tid;
            int row = idx >> 7, col = (idx & 127) * 4;
            *(float4*)&sh_h[row][col] =
                *(const float4*)&g_h1[((size_t)b * NN + j0 + row) * C1 + col];
        }
        __syncthreads();
        // weights: each thread 2 (i,j) pairs x 8 heads; adj loads coalesced in j
        #pragma unroll
        for (int p = 0; p < 2; ++p) {
            const int il = wil + p * 8;
            const int a = adj[((size_t)b * NN + (i0 + il)) * NN + j0 + wjl];
            #pragma unroll
            for (int h = 0; h < NH; ++h) {
                float2 u = sh_ef1[il * NH + h];
                float2 v = sh_ef2[wjl * NH + h];
                float num = fmaxf(u.x * v.x, u.y * v.y);
                num = (a > 0) ? num : 0.0f;
                sh_w[h][il][wjl] = num;
                lacc[p][h] += num;
            }
        }
        __syncthreads();
        // MAC: per j: 2 LDS (h) + 16 broadcast LDS (w) + 32 FFMA
        #pragma unroll 2
        for (int j = 0; j < TJ; ++j) {
            float h0 = sh_h[j][c0], h1v = sh_h[j][c1];
            #pragma unroll
            for (int i = 0; i < TI; ++i) {
                float w = sh_w[head][i][j];
                acc0[i] = fmaf(w, h0, acc0[i]);
                acc1[i] = fmaf(w, h1v, acc1[i]);
            }
        }
    }
    // reduce denominators: warp w accumulated rows il=w and w+8 (lanes = distinct j)
    #pragma unroll
    for (int p = 0; p < 2; ++p)
        #pragma unroll
        for (int h = 0; h < NH; ++h) {
            float v = lacc[p][h];
            #pragma unroll
            for (int s = 16; s; s >>= 1) v += __shfl_down_sync(0xFFFFFFFFu, v, s);
            if (lane == 0) sh_l[(warp + p * 8) * NH + h] = 1.0f / v;
        }
    __syncthreads();
    const float bias0 = bh[head * DD + lane];
    const float bias1 = bh[head * DD + lane + 32];
    #pragma unroll
    for (int i = 0; i < TI; ++i) {
        float inv = sh_l[i * NH + head];
        float z0 = acc0[i] * inv + bias0;
        float z1 = acc1[i] * inv + bias1;
        z0 = (z0 > 0.0f) ? z0 : expm1f(z0);
        z1 = (z1 > 0.0f) ? z1 : expm1f(z1);
        const size_t row = (size_t)b * NN + i0 + i;
        g_z1[row * C1 + c0] = z0;
        g_z1[row * C1 + c1] = z1;
    }
}

// ---------------------------------------------------------------------------
// Aggregation layer2: single head, 128 cols. relu(elu(x)) == max(x, 0).
// ---------------------------------------------------------------------------
__global__ __launch_bounds__(256, 2) void agg2_kernel(const int* __restrict__ adj,
                                                      const float* __restrict__ bo,
                                                      float* __restrict__ out) {
    __shared__ float  sh_h[TJ][NO];     // 16 KB
    __shared__ float  sh_w[TI][TJ];     // 2 KB
    __shared__ float2 sh_ef1[TI];
    __shared__ float2 sh_ef2[TJ];
    __shared__ float  sh_l[TI];

    const int tid = threadIdx.x;
    const int b = blockIdx.y;
    const int i0 = blockIdx.x * TI;
    const int lane = tid & 31, warp = tid >> 5;
    const int c0 = (tid & 63) * 2;      // col pair
    const int g = tid >> 6;             // row group 0..3 (i = g + 4*ii)
    const int wjl = tid & 31, wil = tid >> 5;

    if (tid < TI) sh_ef1[tid] = g_ef1o[(size_t)b * NN + i0 + tid];

    float lacc[2] = {0.0f, 0.0f};
    float acc[4][2] = {};

    for (int j0 = 0; j0 < NN; j0 += TJ) {
        __syncthreads();
        if (tid < TJ) sh_ef2[tid] = g_ef2o[(size_t)b * NN + j0 + tid];
        #pragma unroll
        for (int r = 0; r < 4; ++r) {
            int idx = r * 256 + tid;
            int row = idx >> 5, col = (idx & 31) * 4;
            *(float4*)&sh_h[row][col] =
                *(const float4*)&g_h2[((size_t)b * NN + j0 + row) * NO + col];
        }
        __syncthreads();
        #pragma unroll
        for (int p = 0; p < 2; ++p) {
            const int il = wil + p * 8;
            const int a = adj[((size_t)b * NN + (i0 + il)) * NN + j0 + wjl];
            float2 u = sh_ef1[il], v = sh_ef2[wjl];
            float num = fmaxf(u.x * v.x, u.y * v.y);
            num = (a > 0) ? num : 0.0f;
            sh_w[il][wjl] = num;
            lacc[p] += num;
        }
        __syncthreads();
        #pragma unroll 4
        for (int j = 0; j < TJ; ++j) {
            float2 hv = *(float2*)&sh_h[j][c0];
            #pragma unroll
            for (int ii = 0; ii < 4; ++ii) {
                float w = sh_w[g + ii * 4][j];
                acc[ii][0] = fmaf(w, hv.x, acc[ii][0]);
                acc[ii][1] = fmaf(w, hv.y, acc[ii][1]);
            }
        }
    }
    #pragma unroll
    for (int p = 0; p < 2; ++p) {
        float v = lacc[p];
        #pragma unroll
        for (int s = 16; s; s >>= 1) v += __shfl_down_sync(0xFFFFFFFFu, v, s);
        if (lane == 0) sh_l[warp + p * 8] = 1.0f / v;
    }
    __syncthreads();
    const float b0 = bo[c0], b1 = bo[c0 + 1];
    #pragma unroll
    for (int ii = 0; ii < 4; ++ii) {
        const int i = g + ii * 4;
        float inv = sh_l[i];
        float z0 = fmaxf(acc[ii][0] * inv + b0, 0.0f);
        float z1 = fmaxf(acc[ii][1] * inv + b1, 0.0f);
        *(float2*)&out[((size_t)b * NN + i0 + i) * NO + c0] = make_float2(z0, z1);
    }
}

// ---------------------------------------------------------------------------
extern "C" void kernel_launch(void* const* d_in, const int* in_sizes, int n_in,
                              void* d_out, int out_size) {
    const float* x   = (const float*)d_in[0];
    const int*   adj = (const int*)  d_in[1];
    const float* Wh  = (const float*)d_in[2];
    const float* ah  = (const float*)d_in[3];
    const float* bh  = (const float*)d_in[4];
    const float* Wo  = (const float*)d_in[5];
    const float* ao  = (const float*)d_in[6];
    const float* bo  = (const float*)d_in[7];
    float* out = (float*)d_out;

    const size_t smem1 = (size_t)(TJ * C1 + NH * TI * TJ) * 4   // h tile + w tile
                       + (size_t)(TI * NH + TJ * NH) * 8        // ef1 + ef2
                       + (size_t)(TI * NH) * 4;                 // l
    cudaFuncSetAttribute(agg1_kernel, cudaFuncAttributeMaxDynamicSharedMemorySize,
                         (int)smem1);

    gemm1_kernel<<<dim3(C1 / 64, (BB * NN) / 64), 256>>>(x, Wh);
    scores1_kernel<<<dim3(NN, BB), 256>>>(ah);
    agg1_kernel<<<dim3(NN / TI, BB), 256, smem1>>>(adj, bh);
    gemm2_kernel<<<dim3(NO / 64, (BB * NN) / 64), 256>>>(Wo);
    scores2_kernel<<<dim3(NN, BB), 128>>>(ao);
    agg2_kernel<<<dim3(NN / TI, BB), 256>>>(adj, bo, out);
}

// round 5
// speedup vs baseline: 1.0020x; 1.0020x over previous
#include <cuda_runtime.h>
#include <math.h>

#define BB 4
#define NN 2048
#define NF 256
#define NH 8
#define DD 64
#define C1 512   // NH*DD
#define NO 128

#define TI 16
#define TJ 32

// Scratch (device globals -- no allocations allowed)
__device__ float  g_h1[BB*NN*C1];     // layer1 linear output
__device__ float  g_z1[BB*NN*C1];     // layer1 attention output (= hcat)
__device__ float  g_h2[BB*NN*NO];     // layer2 linear output
__device__ float2 g_ef1[BB*NN*NH];    // (exp(s1), exp(0.1 s1)) per (b,n,head)
__device__ float2 g_ef2[BB*NN*NH];    // (exp(s2), exp(0.1 s2))
__device__ float2 g_ef1o[BB*NN];      // layer2 versions
__device__ float2 g_ef2o[BB*NN];

// ---------------------------------------------------------------------------
// GEMM1: g_h1[m][c] = sum_k X[m][k] * Wh[c/64][k][c%64],  M=8192,K=256,Ncol=512
// 64x64 tiles, BK=16, 256 threads, 4x4 per thread.
// ---------------------------------------------------------------------------
__global__ __launch_bounds__(256) void gemm1_kernel(const float* __restrict__ X,
                                                    const float* __restrict__ Wh) {
    __shared__ float As[16][68];
    __shared__ float Bs[16][68];
    const int tid = threadIdx.x;
    const int tx = tid & 15, ty = tid >> 4;
    const int n0 = blockIdx.x * 64;       // column tile (head-aligned: 64 cols)
    const int m0 = blockIdx.y * 64;       // row tile
    const int head = n0 >> 6;

    const int arow = tid >> 2, akq = tid & 3;   // A loader
    const int brow = tid >> 4, bn4 = tid & 15;  // B loader

    float acc[4][4] = {};

    for (int kk = 0; kk < NF; kk += 16) {
        float4 av = *(const float4*)&X[(size_t)(m0 + arow) * NF + kk + akq * 4];
        As[akq*4+0][arow] = av.x; As[akq*4+1][arow] = av.y;
        As[akq*4+2][arow] = av.z; As[akq*4+3][arow] = av.w;
        float4 bv = *(const float4*)&Wh[(size_t)head*(NF*DD) + (size_t)(kk + brow)*DD + bn4*4];
        *(float4*)&Bs[brow][bn4*4] = bv;
        __syncthreads();
        #pragma unroll
        for (int k = 0; k < 16; ++k) {
            float a0 = As[k][ty*4+0], a1 = As[k][ty*4+1];
            float a2 = As[k][ty*4+2], a3 = As[k][ty*4+3];
            float4 b = *(float4*)&Bs[k][tx*4];
            acc[0][0] = fmaf(a0, b.x, acc[0][0]); acc[0][1] = fmaf(a0, b.y, acc[0][1]);
            acc[0][2] = fmaf(a0, b.z, acc[0][2]); acc[0][3] = fmaf(a0, b.w, acc[0][3]);
            acc[1][0] = fmaf(a1, b.x, acc[1][0]); acc[1][1] = fmaf(a1, b.y, acc[1][1]);
            acc[1][2] = fmaf(a1, b.z, acc[1][2]); acc[1][3] = fmaf(a1, b.w, acc[1][3]);
            acc[2][0] = fmaf(a2, b.x, acc[2][0]); acc[2][1] = fmaf(a2, b.y, acc[2][1]);
            acc[2][2] = fmaf(a2, b.z, acc[2][2]); acc[2][3] = fmaf(a2, b.w, acc[2][3]);
            acc[3][0] = fmaf(a3, b.x, acc[3][0]); acc[3][1] = fmaf(a3, b.y, acc[3][1]);
            acc[3][2] = fmaf(a3, b.z, acc[3][2]); acc[3][3] = fmaf(a3, b.w, acc[3][3]);
        }
        __syncthreads();
    }
    #pragma unroll
    for (int u = 0; u < 4; ++u) {
        float4 v = make_float4(acc[u][0], acc[u][1], acc[u][2], acc[u][3]);
        *(float4*)&g_h1[(size_t)(m0 + ty*4 + u) * C1 + n0 + tx*4] = v;
    }
}

// ---------------------------------------------------------------------------
// GEMM2: g_h2 = g_z1 @ Wo,  M=8192, K=512, Ncol=128
// ---------------------------------------------------------------------------
__global__ __launch_bounds__(256) void gemm2_kernel(const float* __restrict__ Wo) {
    __shared__ float As[16][68];
    __shared__ float Bs[16][68];
    const int tid = threadIdx.x;
    const int tx = tid & 15, ty = tid >> 4;
    const int n0 = blockIdx.x * 64;
    const int m0 = blockIdx.y * 64;

    const int arow = tid >> 2, akq = tid & 3;
    const int brow = tid >> 4, bn4 = tid & 15;

    float acc[4][4] = {};

    for (int kk = 0; kk < C1; kk += 16) {
        float4 av = *(const float4*)&g_z1[(size_t)(m0 + arow) * C1 + kk + akq * 4];
        As[akq*4+0][arow] = av.x; As[akq*4+1][arow] = av.y;
        As[akq*4+2][arow] = av.z; As[akq*4+3][arow] = av.w;
        float4 bv = *(const float4*)&Wo[(size_t)(kk + brow) * NO + n0 + bn4*4];
        *(float4*)&Bs[brow][bn4*4] = bv;
        __syncthreads();
        #pragma unroll
        for (int k = 0; k < 16; ++k) {
            float a0 = As[k][ty*4+0], a1 = As[k][ty*4+1];
            float a2 = As[k][ty*4+2], a3 = As[k][ty*4+3];
            float4 b = *(float4*)&Bs[k][tx*4];
            acc[0][0] = fmaf(a0, b.x, acc[0][0]); acc[0][1] = fmaf(a0, b.y, acc[0][1]);
            acc[0][2] = fmaf(a0, b.z, acc[0][2]); acc[0][3] = fmaf(a0, b.w, acc[0][3]);
            acc[1][0] = fmaf(a1, b.x, acc[1][0]); acc[1][1] = fmaf(a1, b.y, acc[1][1]);
            acc[1][2] = fmaf(a1, b.z, acc[1][2]); acc[1][3] = fmaf(a1, b.w, acc[1][3]);
            acc[2][0] = fmaf(a2, b.x, acc[2][0]); acc[2][1] = fmaf(a2, b.y, acc[2][1]);
            acc[2][2] = fmaf(a2, b.z, acc[2][2]); acc[2][3] = fmaf(a2, b.w, acc[2][3]);
            acc[3][0] = fmaf(a3, b.x, acc[3][0]); acc[3][1] = fmaf(a3, b.y, acc[3][1]);
            acc[3][2] = fmaf(a3, b.z, acc[3][2]); acc[3][3] = fmaf(a3, b.w, acc[3][3]);
        }
        __syncthreads();
    }
    #pragma unroll
    for (int u = 0; u < 4; ++u) {
        float4 v = make_float4(acc[u][0], acc[u][1], acc[u][2], acc[u][3]);
        *(float4*)&g_h2[(size_t)(m0 + ty*4 + u) * NO + n0 + tx*4] = v;
    }
}

// ---------------------------------------------------------------------------
// Scores layer1: per (b,n,head): s1 = h.a1, s2 = h.a2, store exp coefficients
// grid (NN, BB), 256 threads (warp w handles head w)
// ---------------------------------------------------------------------------
__global__ __launch_bounds__(256) void scores1_kernel(const float* __restrict__ ah) {
    const int n = blockIdx.x, b = blockIdx.y;
    const int w = threadIdx.x >> 5, lane = threadIdx.x & 31;
    const size_t row = (size_t)b * NN + n;
    const float* hrow = &g_h1[row * C1 + w * DD];
    float v0 = hrow[lane], v1 = hrow[lane + 32];
    const float* a = &ah[w * 2 * DD];
    float s1 = v0 * a[lane] + v1 * a[lane + 32];
    float s2 = v0 * a[DD + lane] + v1 * a[DD + lane + 32];
    #pragma unroll
    for (int s = 16; s; s >>= 1) {
        s1 += __shfl_down_sync(0xFFFFFFFFu, s1, s);
        s2 += __shfl_down_sync(0xFFFFFFFFu, s2, s);
    }
    if (lane == 0) {
        g_ef1[row * NH + w] = make_float2(expf(s1), expf(0.1f * s1));
        g_ef2[row * NH + w] = make_float2(expf(s2), expf(0.1f * s2));
    }
}

// ---------------------------------------------------------------------------
// Scores layer2: single head over 128 features. grid (NN, BB), 128 threads.
// ---------------------------------------------------------------------------
__global__ __launch_bounds__(128) void scores2_kernel(const float* __restrict__ ao) {
    __shared__ float s1s[128], s2s[128];
    const int n = blockIdx.x, b = blockIdx.y;
    const size_t row = (size_t)b * NN + n;
    const int t = threadIdx.x;
    float v = g_h2[row * NO + t];
    s1s[t] = v * ao[t];
    s2s[t] = v * ao[NO + t];
    __syncthreads();
    for (int s = 64; s; s >>= 1) {
        if (t < s) { s1s[t] += s1s[t + s]; s2s[t] += s2s[t + s]; }
        __syncthreads();
    }
    if (t == 0) {
        float s1 = s1s[0], s2 = s2s[0];
        g_ef1o[row] = make_float2(expf(s1), expf(0.1f * s1));
        g_ef2o[row] = make_float2(expf(s2), expf(0.1f * s2));
    }
}

// ---------------------------------------------------------------------------
// Aggregation layer1 (fused masked-softmax + weighted sum + bias + ELU).
// Block: (b, 16-row tile). 256 threads = 8 warps; warp w owns head w,
// lane owns cols 64w+lane and 64w+lane+32. Denominator accumulated inline,
// normalization deferred to epilogue.
// Dynamic smem layout: h-tile[TJ][C1] | w-tile[NH][TI][TJ] | ef1 | ef2 | l
// ---------------------------------------------------------------------------
__global__ __launch_bounds__(256, 2) void agg1_kernel(const int* __restrict__ adj,
                                                      const float* __restrict__ bh) {
    extern __shared__ float sm[];
    float (*sh_h)[C1] = (float(*)[C1])sm;                               // 16384 f
    float (*sh_w)[TI][TJ] = (float(*)[TI][TJ])(sm + TJ * C1);           // 4096 f
    float2* sh_ef1 = (float2*)(sm + TJ * C1 + NH * TI * TJ);            // 128 f2
    float2* sh_ef2 = sh_ef1 + TI * NH;                                  // 256 f2
    float*  sh_l   = (float*)(sh_ef2 + TJ * NH);                        // 128 f

    const int tid = threadIdx.x;
    const int b = blockIdx.y;
    const int i0 = blockIdx.x * TI;
    const int warp = tid >> 5, lane = tid & 31;
    const int head = warp;
    const int c0 = head * DD + lane, c1 = c0 + 32;
    const int wjl = tid & 31, wil = tid >> 5;   // weight-phase (j,i) mapping

    if (tid < TI * NH)
        sh_ef1[tid] = g_ef1[((size_t)b * NN + i0 + (tid >> 3)) * NH + (tid & 7)];

    float lacc[2][NH];
    #pragma unroll
    for (int p = 0; p < 2; ++p)
        #pragma unroll
        for (int h = 0; h < NH; ++h) lacc[p][h] = 0.0f;
    float acc0[TI], acc1[TI];
    #pragma unroll
    for (int i = 0; i < TI; ++i) { acc0[i] = 0.0f; acc1[i] = 0.0f; }

    for (int j0 = 0; j0 < NN; j0 += TJ) {
        __syncthreads();
        // stage ef2 for this j-tile (tid -> (j = tid>>3, h = tid&7))
        sh_ef2[tid] = g_ef2[((size_t)b * NN + j0 + (tid >> 3)) * NH + (tid & 7)];
        // load h tile (32 x 512 floats, float4)
        #pragma unroll
        for (int r = 0; r < 16; ++r) {
            int idx = r * 256 + tid;
            int row = idx >> 7, col = (idx & 127) * 4;
            *(float4*)&sh_h[row][col] =
                *(const float4*)&g_h1[((size_t)b * NN + j0 + row) * C1 + col];
        }
        __syncthreads();
        // weights: each thread 2 (i,j) pairs x 8 heads; adj loads coalesced in j
        #pragma unroll
        for (int p = 0; p < 2; ++p) {
            const int il = wil + p * 8;
            const int a = adj[((size_t)b * NN + (i0 + il)) * NN + j0 + wjl];
            #pragma unroll
            for (int h = 0; h < NH; ++h) {
                float2 u = sh_ef1[il * NH + h];
                float2 v = sh_ef2[wjl * NH + h];
                float num = fmaxf(u.x * v.x, u.y * v.y);
                num = (a > 0) ? num : 0.0f;
                sh_w[h][il][wjl] = num;
                lacc[p][h] += num;
            }
        }
        __syncthreads();
        // MAC: per j: 2 LDS (h) + 16 broadcast LDS (w) + 32 FFMA
        #pragma unroll 2
        for (int j = 0; j < TJ; ++j) {
            float h0 = sh_h[j][c0], h1v = sh_h[j][c1];
            #pragma unroll
            for (int i = 0; i < TI; ++i) {
                float w = sh_w[head][i][j];
                acc0[i] = fmaf(w, h0, acc0[i]);
                acc1[i] = fmaf(w, h1v, acc1[i]);
            }
        }
    }
    // reduce denominators: warp w accumulated rows il=w and w+8 (lanes = distinct j)
    #pragma unroll
    for (int p = 0; p < 2; ++p)
        #pragma unroll
        for (int h = 0; h < NH; ++h) {
            float v = lacc[p][h];
            #pragma unroll
            for (int s = 16; s; s >>= 1) v += __shfl_down_sync(0xFFFFFFFFu, v, s);
            if (lane == 0) sh_l[(warp + p * 8) * NH + h] = 1.0f / v;
        }
    __syncthreads();
    const float bias0 = bh[head * DD + lane];
    const float bias1 = bh[head * DD + lane + 32];
    #pragma unroll
    for (int i = 0; i < TI; ++i) {
        float inv = sh_l[i * NH + head];
        float z0 = acc0[i] * inv + bias0;
        float z1 = acc1[i] * inv + bias1;
        z0 = (z0 > 0.0f) ? z0 : expm1f(z0);
        z1 = (z1 > 0.0f) ? z1 : expm1f(z1);
        const size_t row = (size_t)b * NN + i0 + i;
        g_z1[row * C1 + c0] = z0;
        g_z1[row * C1 + c1] = z1;
    }
}

// ---------------------------------------------------------------------------
// Aggregation layer2: single head, 128 cols. relu(elu(x)) == max(x, 0).
// ---------------------------------------------------------------------------
__global__ __launch_bounds__(256, 2) void agg2_kernel(const int* __restrict__ adj,
                                                      const float* __restrict__ bo,
                                                      float* __restrict__ out) {
    __shared__ float  sh_h[TJ][NO];     // 16 KB
    __shared__ float  sh_w[TI][TJ];     // 2 KB
    __shared__ float2 sh_ef1[TI];
    __shared__ float2 sh_ef2[TJ];
    __shared__ float  sh_l[TI];

    const int tid = threadIdx.x;
    const int b = blockIdx.y;
    const int i0 = blockIdx.x * TI;
    const int lane = tid & 31, warp = tid >> 5;
    const int c0 = (tid & 63) * 2;      // col pair
    const int g = tid >> 6;             // row group 0..3 (i = g + 4*ii)
    const int wjl = tid & 31, wil = tid >> 5;

    if (tid < TI) sh_ef1[tid] = g_ef1o[(size_t)b * NN + i0 + tid];

    float lacc[2] = {0.0f, 0.0f};
    float acc[4][2] = {};

    for (int j0 = 0; j0 < NN; j0 += TJ) {
        __syncthreads();
        if (tid < TJ) sh_ef2[tid] = g_ef2o[(size_t)b * NN + j0 + tid];
        #pragma unroll
        for (int r = 0; r < 4; ++r) {
            int idx = r * 256 + tid;
            int row = idx >> 5, col = (idx & 31) * 4;
            *(float4*)&sh_h[row][col] =
                *(const float4*)&g_h2[((size_t)b * NN + j0 + row) * NO + col];
        }
        __syncthreads();
        #pragma unroll
        for (int p = 0; p < 2; ++p) {
            const int il = wil + p * 8;
            const int a = adj[((size_t)b * NN + (i0 + il)) * NN + j0 + wjl];
            float2 u = sh_ef1[il], v = sh_ef2[wjl];
            float num = fmaxf(u.x * v.x, u.y * v.y);
            num = (a > 0) ? num : 0.0f;
            sh_w[il][wjl] = num;
            lacc[p] += num;
        }
        __syncthreads();
        #pragma unroll 4
        for (int j = 0; j < TJ; ++j) {
            float2 hv = *(float2*)&sh_h[j][c0];
            #pragma unroll
            for (int ii = 0; ii < 4; ++ii) {
                float w = sh_w[g + ii * 4][j];
                acc[ii][0] = fmaf(w, hv.x, acc[ii][0]);
                acc[ii][1] = fmaf(w, hv.y, acc[ii][1]);
            }
        }
    }
    #pragma unroll
    for (int p = 0; p < 2; ++p) {
        float v = lacc[p];
        #pragma unroll
        for (int s = 16; s; s >>= 1) v += __shfl_down_sync(0xFFFFFFFFu, v, s);
        if (lane == 0) sh_l[warp + p * 8] = 1.0f / v;
    }
    __syncthreads();
    const float b0 = bo[c0], b1 = bo[c0 + 1];
    #pragma unroll
    for (int ii = 0; ii < 4; ++ii) {
        const int i = g + ii * 4;
        float inv = sh_l[i];
        float z0 = fmaxf(acc[ii][0] * inv + b0, 0.0f);
        float z1 = fmaxf(acc[ii][1] * inv + b1, 0.0f);
        *(float2*)&out[((size_t)b * NN + i0 + i) * NO + c0] = make_float2(z0, z1);
    }
}

// ---------------------------------------------------------------------------
extern "C" void kernel_launch(void* const* d_in, const int* in_sizes, int n_in,
                              void* d_out, int out_size) {
    const float* x   = (const float*)d_in[0];
    const int*   adj = (const int*)  d_in[1];
    const float* Wh  = (const float*)d_in[2];
    const float* ah  = (const float*)d_in[3];
    const float* bh  = (const float*)d_in[4];
    const float* Wo  = (const float*)d_in[5];
    const float* ao  = (const float*)d_in[6];
    const float* bo  = (const float*)d_in[7];
    float* out = (float*)d_out;

    const size_t smem1 = (size_t)(TJ * C1 + NH * TI * TJ) * 4   // h tile + w tile
                       + (size_t)(TI * NH + TJ * NH) * 8        // ef1 + ef2
                       + (size_t)(TI * NH) * 4;                 // l
    cudaFuncSetAttribute(agg1_kernel, cudaFuncAttributeMaxDynamicSharedMemorySize,
                         (int)smem1);

    gemm1_kernel<<<dim3(C1 / 64, (BB * NN) / 64), 256>>>(x, Wh);
    scores1_kernel<<<dim3(NN, BB), 256>>>(ah);
    agg1_kernel<<<dim3(NN / TI, BB), 256, smem1>>>(adj, bh);
    gemm2_kernel<<<dim3(NO / 64, (BB * NN) / 64), 256>>>(Wo);
    scores2_kernel<<<dim3(NN, BB), 128>>>(ao);
    agg2_kernel<<<dim3(NN / TI, BB), 256>>>(adj, bo, out);
}

// round 10
// speedup vs baseline: 1.8914x; 1.8876x over previous
#include <cuda_runtime.h>
#include <cuda_bf16.h>
#include <math.h>
#include <stdint.h>

#define BB 4
#define NN 2048
#define NF 256
#define NH 8
#define DD 64
#define C1 512
#define NO 128

__device__ float  g_h1[BB*NN*C1];
__device__ float  g_z1[BB*NN*C1];
__device__ float  g_h2[BB*NN*NO];
__device__ float2 g_ef1[BB*NN*NH];
__device__ float2 g_ef2[BB*NN*NH];
__device__ float2 g_ef1o[BB*NN];
__device__ float2 g_ef2o[BB*NN];
__device__ __nv_bfloat16 g_h1T_hi[BB*C1*NN];
__device__ __nv_bfloat16 g_h1T_lo[BB*C1*NN];
__device__ __nv_bfloat16 g_h2T_hi[BB*NO*NN];
__device__ __nv_bfloat16 g_h2T_lo[BB*NO*NN];

// ---------------- helpers ----------------
__device__ __forceinline__ uint32_t smem_to_u32(const void* p) {
    uint32_t a;
    asm("{ .reg .u64 t; cvta.to.shared.u64 t, %1; cvt.u32.u64 %0, t; }" : "=r"(a) : "l"(p));
    return a;
}
#define LDM_X4(r, addr) \
    asm volatile("ldmatrix.sync.aligned.m8n8.x4.shared.b16 {%0,%1,%2,%3}, [%4];" \
        : "=r"((r)[0]), "=r"((r)[1]), "=r"((r)[2]), "=r"((r)[3]) : "r"(addr))
#define MMA_BF16(d, a, b0, b1) \
    asm volatile("mma.sync.aligned.m16n8k16.row.col.f32.bf16.bf16.f32 " \
        "{%0,%1,%2,%3}, {%4,%5,%6,%7}, {%8,%9}, {%0,%1,%2,%3};" \
        : "+f"((d)[0]), "+f"((d)[1]), "+f"((d)[2]), "+f"((d)[3]) \
        : "r"((a)[0]), "r"((a)[1]), "r"((a)[2]), "r"((a)[3]), "r"(b0), "r"(b1))

// pack two fp32 into bf16x2 (low half = e0)
__device__ __forceinline__ uint32_t pack_bf16(float e0, float e1) {
    uint32_t r;
    asm("cvt.rn.satfinite.bf16x2.f32 %0, %1, %2;" : "=r"(r) : "f"(e1), "f"(e0));
    return r;
}
__device__ __forceinline__ void split_pair(float w0, float w1, uint32_t& hi, uint32_t& lo) {
    hi = pack_bf16(w0, w1);
    float r0 = w0 - __uint_as_float(hi << 16);
    float r1 = w1 - __uint_as_float(hi & 0xFFFF0000u);
    lo = pack_bf16(r0, r1);
}

// ---------------- GEMM1 (SIMT) ----------------
__global__ __launch_bounds__(256) void gemm1_kernel(const float* __restrict__ X,
                                                    const float* __restrict__ Wh) {
    __shared__ float As[16][68];
    __shared__ float Bs[16][68];
    const int tid = threadIdx.x, tx = tid & 15, ty = tid >> 4;
    const int n0 = blockIdx.x * 64, m0 = blockIdx.y * 64, head = n0 >> 6;
    const int arow = tid >> 2, akq = tid & 3, brow = tid >> 4, bn4 = tid & 15;
    float acc[4][4] = {};
    for (int kk = 0; kk < NF; kk += 16) {
        float4 av = *(const float4*)&X[(size_t)(m0 + arow) * NF + kk + akq * 4];
        As[akq*4+0][arow] = av.x; As[akq*4+1][arow] = av.y;
        As[akq*4+2][arow] = av.z; As[akq*4+3][arow] = av.w;
        *(float4*)&Bs[brow][bn4*4] =
            *(const float4*)&Wh[(size_t)head*(NF*DD) + (size_t)(kk + brow)*DD + bn4*4];
        __syncthreads();
        #pragma unroll
        for (int k = 0; k < 16; ++k) {
            float a0 = As[k][ty*4+0], a1 = As[k][ty*4+1];
            float a2 = As[k][ty*4+2], a3 = As[k][ty*4+3];
            float4 b = *(float4*)&Bs[k][tx*4];
            acc[0][0]=fmaf(a0,b.x,acc[0][0]); acc[0][1]=fmaf(a0,b.y,acc[0][1]);
            acc[0][2]=fmaf(a0,b.z,acc[0][2]); acc[0][3]=fmaf(a0,b.w,acc[0][3]);
            acc[1][0]=fmaf(a1,b.x,acc[1][0]); acc[1][1]=fmaf(a1,b.y,acc[1][1]);
            acc[1][2]=fmaf(a1,b.z,acc[1][2]); acc[1][3]=fmaf(a1,b.w,acc[1][3]);
            acc[2][0]=fmaf(a2,b.x,acc[2][0]); acc[2][1]=fmaf(a2,b.y,acc[2][1]);
            acc[2][2]=fmaf(a2,b.z,acc[2][2]); acc[2][3]=fmaf(a2,b.w,acc[2][3]);
            acc[3][0]=fmaf(a3,b.x,acc[3][0]); acc[3][1]=fmaf(a3,b.y,acc[3][1]);
            acc[3][2]=fmaf(a3,b.z,acc[3][2]); acc[3][3]=fmaf(a3,b.w,acc[3][3]);
        }
        __syncthreads();
    }
    #pragma unroll
    for (int u = 0; u < 4; ++u)
        *(float4*)&g_h1[(size_t)(m0 + ty*4 + u) * C1 + n0 + tx*4] =
            make_float4(acc[u][0], acc[u][1], acc[u][2], acc[u][3]);
}

// ---------------- GEMM2 (SIMT) ----------------
__global__ __launch_bounds__(256) void gemm2_kernel(const float* __restrict__ Wo) {
    __shared__ float As[16][68];
    __shared__ float Bs[16][68];
    const int tid = threadIdx.x, tx = tid & 15, ty = tid >> 4;
    const int n0 = blockIdx.x * 64, m0 = blockIdx.y * 64;
    const int arow = tid >> 2, akq = tid & 3, brow = tid >> 4, bn4 = tid & 15;
    float acc[4][4] = {};
    for (int kk = 0; kk < C1; kk += 16) {
        float4 av = *(const float4*)&g_z1[(size_t)(m0 + arow) * C1 + kk + akq * 4];
        As[akq*4+0][arow] = av.x; As[akq*4+1][arow] = av.y;
        As[akq*4+2][arow] = av.z; As[akq*4+3][arow] = av.w;
        *(float4*)&Bs[brow][bn4*4] = *(const float4*)&Wo[(size_t)(kk + brow) * NO + n0 + bn4*4];
        __syncthreads();
        #pragma unroll
        for (int k = 0; k < 16; ++k) {
            float a0 = As[k][ty*4+0], a1 = As[k][ty*4+1];
            float a2 = As[k][ty*4+2], a3 = As[k][ty*4+3];
            float4 b = *(float4*)&Bs[k][tx*4];
            acc[0][0]=fmaf(a0,b.x,acc[0][0]); acc[0][1]=fmaf(a0,b.y,acc[0][1]);
            acc[0][2]=fmaf(a0,b.z,acc[0][2]); acc[0][3]=fmaf(a0,b.w,acc[0][3]);
            acc[1][0]=fmaf(a1,b.x,acc[1][0]); acc[1][1]=fmaf(a1,b.y,acc[1][1]);
            acc[1][2]=fmaf(a1,b.z,acc[1][2]); acc[1][3]=fmaf(a1,b.w,acc[1][3]);
            acc[2][0]=fmaf(a2,b.x,acc[2][0]); acc[2][1]=fmaf(a2,b.y,acc[2][1]);
            acc[2][2]=fmaf(a2,b.z,acc[2][2]); acc[2][3]=fmaf(a2,b.w,acc[2][3]);
            acc[3][0]=fmaf(a3,b.x,acc[3][0]); acc[3][1]=fmaf(a3,b.y,acc[3][1]);
            acc[3][2]=fmaf(a3,b.z,acc[3][2]); acc[3][3]=fmaf(a3,b.w,acc[3][3]);
        }
        __syncthreads();
    }
    #pragma unroll
    for (int u = 0; u < 4; ++u)
        *(float4*)&g_h2[(size_t)(m0 + ty*4 + u) * NO + n0 + tx*4] =
            make_float4(acc[u][0], acc[u][1], acc[u][2], acc[u][3]);
}

// ---------------- scores ----------------
__global__ __launch_bounds__(256) void scores1_kernel(const float* __restrict__ ah) {
    const int n = blockIdx.x, b = blockIdx.y;
    const int w = threadIdx.x >> 5, lane = threadIdx.x & 31;
    const size_t row = (size_t)b * NN + n;
    const float* hrow = &g_h1[row * C1 + w * DD];
    float v0 = hrow[lane], v1 = hrow[lane + 32];
    const float* a = &ah[w * 2 * DD];
    float s1 = v0 * a[lane] + v1 * a[lane + 32];
    float s2 = v0 * a[DD + lane] + v1 * a[DD + lane + 32];
    #pragma unroll
    for (int s = 16; s; s >>= 1) {
        s1 += __shfl_down_sync(0xFFFFFFFFu, s1, s);
        s2 += __shfl_down_sync(0xFFFFFFFFu, s2, s);
    }
    if (lane == 0) {
        g_ef1[row * NH + w] = make_float2(expf(s1), expf(0.1f * s1));
        g_ef2[row * NH + w] = make_float2(expf(s2), expf(0.1f * s2));
    }
}
__global__ __launch_bounds__(128) void scores2_kernel(const float* __restrict__ ao) {
    __shared__ float s1s[128], s2s[128];
    const int n = blockIdx.x, b = blockIdx.y;
    const size_t row = (size_t)b * NN + n;
    const int t = threadIdx.x;
    float v = g_h2[row * NO + t];
    s1s[t] = v * ao[t];
    s2s[t] = v * ao[NO + t];
    __syncthreads();
    for (int s = 64; s; s >>= 1) {
        if (t < s) { s1s[t] += s1s[t + s]; s2s[t] += s2s[t + s]; }
        __syncthreads();
    }
    if (t == 0) {
        g_ef1o[row] = make_float2(expf(s1s[0]), expf(0.1f * s1s[0]));
        g_ef2o[row] = make_float2(expf(s2s[0]), expf(0.1f * s2s[0]));
    }
}

// ---------------- transpose + bf16 split ----------------
__device__ __forceinline__ void trans_split(const float* __restrict__ src,
                                            __nv_bfloat16* __restrict__ dhi,
                                            __nv_bfloat16* __restrict__ dlo, int C) {
    __shared__ float tsm[32][33];
    const int lane = threadIdx.x & 31, ty = threadIdx.x >> 5;
    const int n0 = blockIdx.x * 32, c0 = blockIdx.y * 32, b = blockIdx.z;
    #pragma unroll
    for (int r = 0; r < 4; ++r)
        tsm[ty + r*8][lane] = src[((size_t)b*NN + n0 + ty + r*8)*C + c0 + lane];
    __syncthreads();
    #pragma unroll
    for (int r = 0; r < 4; ++r) {
        float v = tsm[lane][ty + r*8];
        __nv_bfloat16 h = __float2bfloat16(v);
        __nv_bfloat16 lo = __float2bfloat16(v - __bfloat162float(h));
        size_t o = ((size_t)b*C + c0 + ty + r*8)*NN + n0 + lane;
        dhi[o] = h; dlo[o] = lo;
    }
}
__global__ __launch_bounds__(256) void trans1_kernel() { trans_split(g_h1, g_h1T_hi, g_h1T_lo, C1); }
__global__ __launch_bounds__(256) void trans2_kernel() { trans_split(g_h2, g_h2T_hi, g_h2T_lo, NO); }

// ---------------- agg1 via mma.sync (bf16 hi/lo, 3 passes) ----------------
// block = (head, 128 i-rows, b); 8 warps; warp w owns rows iw..iw+16, all 64 cols.
// K loop: 32 j-tiles of 64.  smem: Bt hi/lo [64 c][72], per-warp W hi/lo [16][72].
__global__ __launch_bounds__(256) void agg1_mma_kernel(const int* __restrict__ adj,
                                                       const float* __restrict__ bh) {
    extern __shared__ __align__(16) char dsm[];
    __nv_bfloat16* sBhi = (__nv_bfloat16*)dsm;           // 64*72
    __nv_bfloat16* sBlo = sBhi + 64*72;                  // 64*72
    __nv_bfloat16* sWb  = sBlo + 64*72;                  // 8*2*16*72
    float2* sef2 = (float2*)(sWb + 8*2*16*72);           // 64

    const int tid = threadIdx.x, warp = tid >> 5, lane = tid & 31;
    const int head = blockIdx.x, i0 = blockIdx.y * 128, b = blockIdx.z;
    const int iw = i0 + warp * 16;
    __nv_bfloat16* wh = sWb + warp * (2*16*72);
    __nv_bfloat16* wl = wh + 16*72;
    const uint32_t whA = smem_to_u32(wh), wlA = smem_to_u32(wl);
    const uint32_t bhiA = smem_to_u32(sBhi), bloA = smem_to_u32(sBlo);

    const int rq = lane >> 2, cq = lane & 3;
    const float2 u0 = g_ef1[((size_t)b*NN + iw + rq)*NH + head];
    const float2 u1 = g_ef1[((size_t)b*NN + iw + rq + 8)*NH + head];
    float lac0 = 0.0f, lac1 = 0.0f;
    float acc[8][4];
    #pragma unroll
    for (int i = 0; i < 8; ++i)
        #pragma unroll
        for (int j = 0; j < 4; ++j) acc[i][j] = 0.0f;

    for (int jt = 0; jt < 32; ++jt) {
        const int j0 = jt * 64;
        __syncthreads();
        if (tid < 64) sef2[tid] = g_ef2[((size_t)b*NN + j0 + tid)*NH + head];
        #pragma unroll
        for (int rr = 0; rr < 2; ++rr) {
            int idx = tid + rr*256;
            int row = idx >> 3, ch = idx & 7;
            size_t so = ((size_t)(b*C1 + head*DD + row))*NN + j0 + ch*8;
            *(uint4*)(sBhi + row*72 + ch*8) = *(const uint4*)(g_h1T_hi + so);
            *(uint4*)(sBlo + row*72 + ch*8) = *(const uint4*)(g_h1T_lo + so);
        }
        __syncthreads();

        // weight generation (warp-private tile)
        #pragma unroll
        for (int p = 0; p < 2; ++p) {
            const int r = rq + p*8;
            const float2 uu = p ? u1 : u0;
            const int4* arow = (const int4*)(adj + ((size_t)b*NN + iw + r)*NN + j0 + cq*16);
            uint32_t* whr = (uint32_t*)(wh + r*72) + cq*8;
            uint32_t* wlr = (uint32_t*)(wl + r*72) + cq*8;
            float ls = 0.0f;
            #pragma unroll
            for (int q = 0; q < 4; ++q) {
                int4 a4 = arow[q];
                int jj = cq*16 + q*4;
                float2 v0 = sef2[jj+0], v1 = sef2[jj+1];
                float2 v2 = sef2[jj+2], v3 = sef2[jj+3];
                float w0 = (a4.x > 0) ? fmaxf(uu.x*v0.x, uu.y*v0.y) : 0.0f;
                float w1 = (a4.y > 0) ? fmaxf(uu.x*v1.x, uu.y*v1.y) : 0.0f;
                float w2 = (a4.z > 0) ? fmaxf(uu.x*v2.x, uu.y*v2.y) : 0.0f;
                float w3 = (a4.w > 0) ? fmaxf(uu.x*v3.x, uu.y*v3.y) : 0.0f;
                ls += (w0 + w1) + (w2 + w3);
                uint32_t h0, l0, h1, l1;
                split_pair(w0, w1, h0, l0);
                split_pair(w2, w3, h1, l1);
                whr[q*2] = h0; whr[q*2+1] = h1;
                wlr[q*2] = l0; wlr[q*2+1] = l1;
            }
            if (p) lac1 += ls; else lac0 += ls;
        }
        __syncwarp();

        // MMAs: 4 k-steps of 16
        #pragma unroll
        for (int ks = 0; ks < 4; ++ks) {
            uint32_t ahi[4], alo[4];
            uint32_t aoff = (uint32_t)(((lane & 15)*72 + ks*16 + (lane >> 4)*8) * 2);
            LDM_X4(ahi, whA + aoff);
            LDM_X4(alo, wlA + aoff);
            #pragma unroll
            for (int np = 0; np < 4; ++np) {
                uint32_t boff = (uint32_t)(((np*16 + (lane & 15))*72 + ks*16 + (lane >> 4)*8) * 2);
                uint32_t bh4[4], bl4[4];
                LDM_X4(bh4, bhiA + boff);
                LDM_X4(bl4, bloA + boff);
                MMA_BF16(acc[2*np],   ahi, bh4[0], bh4[2]);
                MMA_BF16(acc[2*np+1], ahi, bh4[1], bh4[3]);
                MMA_BF16(acc[2*np],   ahi, bl4[0], bl4[2]);
                MMA_BF16(acc[2*np+1], ahi, bl4[1], bl4[3]);
                MMA_BF16(acc[2*np],   alo, bh4[0], bh4[2]);
                MMA_BF16(acc[2*np+1], alo, bh4[1], bh4[3]);
            }
        }
    }
    lac0 += __shfl_xor_sync(0xFFFFFFFFu, lac0, 1);
    lac0 += __shfl_xor_sync(0xFFFFFFFFu, lac0, 2);
    lac1 += __shfl_xor_sync(0xFFFFFFFFu, lac1, 1);
    lac1 += __shfl_xor_sync(0xFFFFFFFFu, lac1, 2);
    const float inv0 = 1.0f / lac0, inv1 = 1.0f / lac1;
    const int r0 = iw + rq, r1 = r0 + 8;
    #pragma unroll
    for (int nt = 0; nt < 8; ++nt) {
        const int c = nt*8 + cq*2;
        const float bb0 = bh[head*DD + c], bb1 = bh[head*DD + c + 1];
        float z00 = acc[nt][0]*inv0 + bb0, z01 = acc[nt][1]*inv0 + bb1;
        float z10 = acc[nt][2]*inv1 + bb0, z11 = acc[nt][3]*inv1 + bb1;
        z00 = (z00 > 0.0f) ? z00 : expm1f(z00);
        z01 = (z01 > 0.0f) ? z01 : expm1f(z01);
        z10 = (z10 > 0.0f) ? z10 : expm1f(z10);
        z11 = (z11 > 0.0f) ? z11 : expm1f(z11);
        *(float2*)&g_z1[((size_t)b*NN + r0)*C1 + head*DD + c] = make_float2(z00, z01);
        *(float2*)&g_z1[((size_t)b*NN + r1)*C1 + head*DD + c] = make_float2(z10, z11);
    }
}

// ---------------- agg2 via mma.sync (N=128) ----------------
// block = (64 i-rows, b); 4 warps; warp w rows iw..iw+16, 128 cols (16 ntiles).
__global__ __launch_bounds__(128) void agg2_mma_kernel(const int* __restrict__ adj,
                                                       const float* __restrict__ bo,
                                                       float* __restrict__ out) {
    extern __shared__ __align__(16) char dsm[];
    __nv_bfloat16* sBhi = (__nv_bfloat16*)dsm;           // 128*72
    __nv_bfloat16* sBlo = sBhi + 128*72;
    __nv_bfloat16* sWb  = sBlo + 128*72;                 // 4*2*16*72
    float2* sef2 = (float2*)(sWb + 4*2*16*72);           // 64

    const int tid = threadIdx.x, warp = tid >> 5, lane = tid & 31;
    const int i0 = blockIdx.x * 64, b = blockIdx.y;
    const int iw = i0 + warp * 16;
    __nv_bfloat16* wh = sWb + warp * (2*16*72);
    __nv_bfloat16* wl = wh + 16*72;
    const uint32_t whA = smem_to_u32(wh), wlA = smem_to_u32(wl);
    const uint32_t bhiA = smem_to_u32(sBhi), bloA = smem_to_u32(sBlo);

    const int rq = lane >> 2, cq = lane & 3;
    const float2 u0 = g_ef1o[(size_t)b*NN + iw + rq];
    const float2 u1 = g_ef1o[(size_t)b*NN + iw + rq + 8];
    float lac0 = 0.0f, lac1 = 0.0f;
    float acc[16][4];
    #pragma unroll
    for (int i = 0; i < 16; ++i)
        #pragma unroll
        for (int j = 0; j < 4; ++j) acc[i][j] = 0.0f;

    for (int jt = 0; jt < 32; ++jt) {
        const int j0 = jt * 64;
        __syncthreads();
        if (tid < 64) sef2[tid] = g_ef2o[(size_t)b*NN + j0 + tid];
        #pragma unroll
        for (int rr = 0; rr < 8; ++rr) {
            int idx = tid + rr*128;
            int row = idx >> 3, ch = idx & 7;
            size_t so = ((size_t)(b*NO + row))*NN + j0 + ch*8;
            *(uint4*)(sBhi + row*72 + ch*8) = *(const uint4*)(g_h2T_hi + so);
            *(uint4*)(sBlo + row*72 + ch*8) = *(const uint4*)(g_h2T_lo + so);
        }
        __syncthreads();

        #pragma unroll
        for (int p = 0; p < 2; ++p) {
            const int r = rq + p*8;
            const float2 uu = p ? u1 : u0;
            const int4* arow = (const int4*)(adj + ((size_t)b*NN + iw + r)*NN + j0 + cq*16);
            uint32_t* whr = (uint32_t*)(wh + r*72) + cq*8;
            uint32_t* wlr = (uint32_t*)(wl + r*72) + cq*8;
            float ls = 0.0f;
            #pragma unroll
            for (int q = 0; q < 4; ++q) {
                int4 a4 = arow[q];
                int jj = cq*16 + q*4;
                float2 v0 = sef2[jj+0], v1 = sef2[jj+1];
                float2 v2 = sef2[jj+2], v3 = sef2[jj+3];
                float w0 = (a4.x > 0) ? fmaxf(uu.x*v0.x, uu.y*v0.y) : 0.0f;
                float w1 = (a4.y > 0) ? fmaxf(uu.x*v1.x, uu.y*v1.y) : 0.0f;
                float w2 = (a4.z > 0) ? fmaxf(uu.x*v2.x, uu.y*v2.y) : 0.0f;
                float w3 = (a4.w > 0) ? fmaxf(uu.x*v3.x, uu.y*v3.y) : 0.0f;
                ls += (w0 + w1) + (w2 + w3);
                uint32_t h0, l0, h1, l1;
                split_pair(w0, w1, h0, l0);
                split_pair(w2, w3, h1, l1);
                whr[q*2] = h0; whr[q*2+1] = h1;
                wlr[q*2] = l0; wlr[q*2+1] = l1;
            }
            if (p) lac1 += ls; else lac0 += ls;
        }
        __syncwarp();

        #pragma unroll
        for (int ks = 0; ks < 4; ++ks) {
            uint32_t ahi[4], alo[4];
            uint32_t aoff = (uint32_t)(((lane & 15)*72 + ks*16 + (lane >> 4)*8) * 2);
            LDM_X4(ahi, whA + aoff);
            LDM_X4(alo, wlA + aoff);
            #pragma unroll
            for (int np = 0; np < 8; ++np) {
                uint32_t boff = (uint32_t)(((np*16 + (lane & 15))*72 + ks*16 + (lane >> 4)*8) * 2);
                uint32_t bh4[4], bl4[4];
                LDM_X4(bh4, bhiA + boff);
                LDM_X4(bl4, bloA + boff);
                MMA_BF16(acc[2*np],   ahi, bh4[0], bh4[2]);
                MMA_BF16(acc[2*np+1], ahi, bh4[1], bh4[3]);
                MMA_BF16(acc[2*np],   ahi, bl4[0], bl4[2]);
                MMA_BF16(acc[2*np+1], ahi, bl4[1], bl4[3]);
                MMA_BF16(acc[2*np],   alo, bh4[0], bh4[2]);
                MMA_BF16(acc[2*np+1], alo, bh4[1], bh4[3]);
            }
        }
    }
    lac0 += __shfl_xor_sync(0xFFFFFFFFu, lac0, 1);
    lac0 += __shfl_xor_sync(0xFFFFFFFFu, lac0, 2);
    lac1 += __shfl_xor_sync(0xFFFFFFFFu, lac1, 1);
    lac1 += __shfl_xor_sync(0xFFFFFFFFu, lac1, 2);
    const float inv0 = 1.0f / lac0, inv1 = 1.0f / lac1;
    const int r0 = iw + rq, r1 = r0 + 8;
    #pragma unroll
    for (int nt = 0; nt < 16; ++nt) {
        const int c = nt*8 + cq*2;
        const float bb0 = bo[c], bb1 = bo[c + 1];
        float z00 = fmaxf(acc[nt][0]*inv0 + bb0, 0.0f);
        float z01 = fmaxf(acc[nt][1]*inv0 + bb1, 0.0f);
        float z10 = fmaxf(acc[nt][2]*inv1 + bb0, 0.0f);
        float z11 = fmaxf(acc[nt][3]*inv1 + bb1, 0.0f);
        *(float2*)&out[((size_t)b*NN + r0)*NO + c] = make_float2(z00, z01);
        *(float2*)&out[((size_t)b*NN + r1)*NO + c] = make_float2(z10, z11);
    }
}

// ---------------------------------------------------------------------------
extern "C" void kernel_launch(void* const* d_in, const int* in_sizes, int n_in,
                              void* d_out, int out_size) {
    const float* x   = (const float*)d_in[0];
    const int*   adj = (const int*)  d_in[1];
    const float* Wh  = (const float*)d_in[2];
    const float* ah  = (const float*)d_in[3];
    const float* bh  = (const float*)d_in[4];
    const float* Wo  = (const float*)d_in[5];
    const float* ao  = (const float*)d_in[6];
    const float* bo  = (const float*)d_in[7];
    float* out = (float*)d_out;

    // agg1: B(2*64*72*2) + W(8*2*16*72*2) + ef2(64*8) = 18432 + 36864 + 512
    // agg2: B(2*128*72*2) + W(4*2*16*72*2) + ef2      = 36864 + 18432 + 512
    const int smem_agg = 18432 + 36864 + 512;
    cudaFuncSetAttribute(agg1_mma_kernel, cudaFuncAttributeMaxDynamicSharedMemorySize, smem_agg);
    cudaFuncSetAttribute(agg2_mma_kernel, cudaFuncAttributeMaxDynamicSharedMemorySize, smem_agg);

    gemm1_kernel<<<dim3(C1 / 64, (BB * NN) / 64), 256>>>(x, Wh);
    scores1_kernel<<<dim3(NN, BB), 256>>>(ah);
    trans1_kernel<<<dim3(NN / 32, C1 / 32, BB), 256>>>();
    agg1_mma_kernel<<<dim3(NH, NN / 128, BB), 256, smem_agg>>>(adj, bh);
    gemm2_kernel<<<dim3(NO / 64, (BB * NN) / 64), 256>>>(Wo);
    scores2_kernel<<<dim3(NN, BB), 128>>>(ao);
    trans2_kernel<<<dim3(NN / 32, NO / 32, BB), 256>>>();
    agg2_mma_kernel<<<dim3(NN / 64, BB), 128, smem_agg>>>(adj, bo, out);
}

// round 11
// speedup vs baseline: 2.3041x; 1.2182x over previous
#include <cuda_runtime.h>
#include <cuda_bf16.h>
#include <math.h>
#include <stdint.h>

#define BB 4
#define NN 2048
#define NF 256
#define NH 8
#define DD 64
#define C1 512
#define NO 128

__device__ float  g_h1[BB*NN*C1];
__device__ float  g_z1[BB*NN*C1];
__device__ float  g_h2[BB*NN*NO];
__device__ float2 g_ef1[BB*NN*NH];
__device__ float2 g_ef2[BB*NN*NH];
__device__ float2 g_ef1o[BB*NN];
__device__ float2 g_ef2o[BB*NN];
__device__ __nv_bfloat16 g_h1T_hi[BB*C1*NN];
__device__ __nv_bfloat16 g_h1T_lo[BB*C1*NN];
__device__ __nv_bfloat16 g_h2T_hi[BB*NO*NN];
__device__ __nv_bfloat16 g_h2T_lo[BB*NO*NN];
__device__ uint32_t g_adjp[BB*NN*(NN/32)];   // bit-packed adjacency

// ---------------- helpers ----------------
__device__ __forceinline__ uint32_t smem_to_u32(const void* p) {
    uint32_t a;
    asm("{ .reg .u64 t; cvta.to.shared.u64 t, %1; cvt.u32.u64 %0, t; }" : "=r"(a) : "l"(p));
    return a;
}
#define LDM_X4(r, addr) \
    asm volatile("ldmatrix.sync.aligned.m8n8.x4.shared.b16 {%0,%1,%2,%3}, [%4];" \
        : "=r"((r)[0]), "=r"((r)[1]), "=r"((r)[2]), "=r"((r)[3]) : "r"(addr))
#define MMA_BF16(d, a, b0, b1) \
    asm volatile("mma.sync.aligned.m16n8k16.row.col.f32.bf16.bf16.f32 " \
        "{%0,%1,%2,%3}, {%4,%5,%6,%7}, {%8,%9}, {%0,%1,%2,%3};" \
        : "+f"((d)[0]), "+f"((d)[1]), "+f"((d)[2]), "+f"((d)[3]) \
        : "r"((a)[0]), "r"((a)[1]), "r"((a)[2]), "r"((a)[3]), "r"(b0), "r"(b1))

__device__ __forceinline__ uint32_t pack_bf16(float e0, float e1) {
    uint32_t r;
    asm("cvt.rn.satfinite.bf16x2.f32 %0, %1, %2;" : "=r"(r) : "f"(e1), "f"(e0));
    return r;
}
__device__ __forceinline__ void split_pair(float w0, float w1, uint32_t& hi, uint32_t& lo) {
    hi = pack_bf16(w0, w1);
    float r0 = w0 - __uint_as_float(hi << 16);
    float r1 = w1 - __uint_as_float(hi & 0xFFFF0000u);
    lo = pack_bf16(r0, r1);
}

// ---------------- adj bit-pack ----------------
__global__ __launch_bounds__(256) void pack_adj_kernel(const int* __restrict__ adj) {
    const int lane = threadIdx.x & 31, warp = threadIdx.x >> 5;
    const int row = blockIdx.x * 8 + warp;               // 0 .. BB*NN-1
    const size_t base = (size_t)row * NN;
    uint32_t w0 = 0, w1 = 0;
    #pragma unroll 8
    for (int g = 0; g < 64; ++g) {
        uint32_t bits = __ballot_sync(0xFFFFFFFFu, adj[base + g*32 + lane] > 0);
        if (g < 32) { if (lane == g) w0 = bits; }
        else        { if (lane == g - 32) w1 = bits; }
    }
    g_adjp[(size_t)row*64 + lane] = w0;
    g_adjp[(size_t)row*64 + 32 + lane] = w1;
}

// ---------------- GEMM1 (SIMT) ----------------
__global__ __launch_bounds__(256) void gemm1_kernel(const float* __restrict__ X,
                                                    const float* __restrict__ Wh) {
    __shared__ float As[16][68];
    __shared__ float Bs[16][68];
    const int tid = threadIdx.x, tx = tid & 15, ty = tid >> 4;
    const int n0 = blockIdx.x * 64, m0 = blockIdx.y * 64, head = n0 >> 6;
    const int arow = tid >> 2, akq = tid & 3, brow = tid >> 4, bn4 = tid & 15;
    float acc[4][4] = {};
    for (int kk = 0; kk < NF; kk += 16) {
        float4 av = *(const float4*)&X[(size_t)(m0 + arow) * NF + kk + akq * 4];
        As[akq*4+0][arow] = av.x; As[akq*4+1][arow] = av.y;
        As[akq*4+2][arow] = av.z; As[akq*4+3][arow] = av.w;
        *(float4*)&Bs[brow][bn4*4] =
            *(const float4*)&Wh[(size_t)head*(NF*DD) + (size_t)(kk + brow)*DD + bn4*4];
        __syncthreads();
        #pragma unroll
        for (int k = 0; k < 16; ++k) {
            float a0 = As[k][ty*4+0], a1 = As[k][ty*4+1];
            float a2 = As[k][ty*4+2], a3 = As[k][ty*4+3];
            float4 b = *(float4*)&Bs[k][tx*4];
            acc[0][0]=fmaf(a0,b.x,acc[0][0]); acc[0][1]=fmaf(a0,b.y,acc[0][1]);
            acc[0][2]=fmaf(a0,b.z,acc[0][2]); acc[0][3]=fmaf(a0,b.w,acc[0][3]);
            acc[1][0]=fmaf(a1,b.x,acc[1][0]); acc[1][1]=fmaf(a1,b.y,acc[1][1]);
            acc[1][2]=fmaf(a1,b.z,acc[1][2]); acc[1][3]=fmaf(a1,b.w,acc[1][3]);
            acc[2][0]=fmaf(a2,b.x,acc[2][0]); acc[2][1]=fmaf(a2,b.y,acc[2][1]);
            acc[2][2]=fmaf(a2,b.z,acc[2][2]); acc[2][3]=fmaf(a2,b.w,acc[2][3]);
            acc[3][0]=fmaf(a3,b.x,acc[3][0]); acc[3][1]=fmaf(a3,b.y,acc[3][1]);
            acc[3][2]=fmaf(a3,b.z,acc[3][2]); acc[3][3]=fmaf(a3,b.w,acc[3][3]);
        }
        __syncthreads();
    }
    #pragma unroll
    for (int u = 0; u < 4; ++u)
        *(float4*)&g_h1[(size_t)(m0 + ty*4 + u) * C1 + n0 + tx*4] =
            make_float4(acc[u][0], acc[u][1], acc[u][2], acc[u][3]);
}

// ---------------- GEMM2 (SIMT) ----------------
__global__ __launch_bounds__(256) void gemm2_kernel(const float* __restrict__ Wo) {
    __shared__ float As[16][68];
    __shared__ float Bs[16][68];
    const int tid = threadIdx.x, tx = tid & 15, ty = tid >> 4;
    const int n0 = blockIdx.x * 64, m0 = blockIdx.y * 64;
    const int arow = tid >> 2, akq = tid & 3, brow = tid >> 4, bn4 = tid & 15;
    float acc[4][4] = {};
    for (int kk = 0; kk < C1; kk += 16) {
        float4 av = *(const float4*)&g_z1[(size_t)(m0 + arow) * C1 + kk + akq * 4];
        As[akq*4+0][arow] = av.x; As[akq*4+1][arow] = av.y;
        As[akq*4+2][arow] = av.z; As[akq*4+3][arow] = av.w;
        *(float4*)&Bs[brow][bn4*4] = *(const float4*)&Wo[(size_t)(kk + brow) * NO + n0 + bn4*4];
        __syncthreads();
        #pragma unroll
        for (int k = 0; k < 16; ++k) {
            float a0 = As[k][ty*4+0], a1 = As[k][ty*4+1];
            float a2 = As[k][ty*4+2], a3 = As[k][ty*4+3];
            float4 b = *(float4*)&Bs[k][tx*4];
            acc[0][0]=fmaf(a0,b.x,acc[0][0]); acc[0][1]=fmaf(a0,b.y,acc[0][1]);
            acc[0][2]=fmaf(a0,b.z,acc[0][2]); acc[0][3]=fmaf(a0,b.w,acc[0][3]);
            acc[1][0]=fmaf(a1,b.x,acc[1][0]); acc[1][1]=fmaf(a1,b.y,acc[1][1]);
            acc[1][2]=fmaf(a1,b.z,acc[1][2]); acc[1][3]=fmaf(a1,b.w,acc[1][3]);
            acc[2][0]=fmaf(a2,b.x,acc[2][0]); acc[2][1]=fmaf(a2,b.y,acc[2][1]);
            acc[2][2]=fmaf(a2,b.z,acc[2][2]); acc[2][3]=fmaf(a2,b.w,acc[2][3]);
            acc[3][0]=fmaf(a3,b.x,acc[3][0]); acc[3][1]=fmaf(a3,b.y,acc[3][1]);
            acc[3][2]=fmaf(a3,b.z,acc[3][2]); acc[3][3]=fmaf(a3,b.w,acc[3][3]);
        }
        __syncthreads();
    }
    #pragma unroll
    for (int u = 0; u < 4; ++u)
        *(float4*)&g_h2[(size_t)(m0 + ty*4 + u) * NO + n0 + tx*4] =
            make_float4(acc[u][0], acc[u][1], acc[u][2], acc[u][3]);
}

// ---------------- scores ----------------
__global__ __launch_bounds__(256) void scores1_kernel(const float* __restrict__ ah) {
    const int n = blockIdx.x, b = blockIdx.y;
    const int w = threadIdx.x >> 5, lane = threadIdx.x & 31;
    const size_t row = (size_t)b * NN + n;
    const float* hrow = &g_h1[row * C1 + w * DD];
    float v0 = hrow[lane], v1 = hrow[lane + 32];
    const float* a = &ah[w * 2 * DD];
    float s1 = v0 * a[lane] + v1 * a[lane + 32];
    float s2 = v0 * a[DD + lane] + v1 * a[DD + lane + 32];
    #pragma unroll
    for (int s = 16; s; s >>= 1) {
        s1 += __shfl_down_sync(0xFFFFFFFFu, s1, s);
        s2 += __shfl_down_sync(0xFFFFFFFFu, s2, s);
    }
    if (lane == 0) {
        g_ef1[row * NH + w] = make_float2(expf(s1), expf(0.1f * s1));
        g_ef2[row * NH + w] = make_float2(expf(s2), expf(0.1f * s2));
    }
}
__global__ __launch_bounds__(128) void scores2_kernel(const float* __restrict__ ao) {
    __shared__ float s1s[128], s2s[128];
    const int n = blockIdx.x, b = blockIdx.y;
    const size_t row = (size_t)b * NN + n;
    const int t = threadIdx.x;
    float v = g_h2[row * NO + t];
    s1s[t] = v * ao[t];
    s2s[t] = v * ao[NO + t];
    __syncthreads();
    for (int s = 64; s; s >>= 1) {
        if (t < s) { s1s[t] += s1s[t + s]; s2s[t] += s2s[t + s]; }
        __syncthreads();
    }
    if (t == 0) {
        g_ef1o[row] = make_float2(expf(s1s[0]), expf(0.1f * s1s[0]));
        g_ef2o[row] = make_float2(expf(s2s[0]), expf(0.1f * s2s[0]));
    }
}

// ---------------- transpose + bf16 split ----------------
__device__ __forceinline__ void trans_split(const float* __restrict__ src,
                                            __nv_bfloat16* __restrict__ dhi,
                                            __nv_bfloat16* __restrict__ dlo, int C) {
    __shared__ float tsm[32][33];
    const int lane = threadIdx.x & 31, ty = threadIdx.x >> 5;
    const int n0 = blockIdx.x * 32, c0 = blockIdx.y * 32, b = blockIdx.z;
    #pragma unroll
    for (int r = 0; r < 4; ++r)
        tsm[ty + r*8][lane] = src[((size_t)b*NN + n0 + ty + r*8)*C + c0 + lane];
    __syncthreads();
    #pragma unroll
    for (int r = 0; r < 4; ++r) {
        float v = tsm[lane][ty + r*8];
        __nv_bfloat16 h = __float2bfloat16(v);
        __nv_bfloat16 lo = __float2bfloat16(v - __bfloat162float(h));
        size_t o = ((size_t)b*C + c0 + ty + r*8)*NN + n0 + lane;
        dhi[o] = h; dlo[o] = lo;
    }
}
__global__ __launch_bounds__(256) void trans1_kernel() { trans_split(g_h1, g_h1T_hi, g_h1T_lo, C1); }
__global__ __launch_bounds__(256) void trans2_kernel() { trans_split(g_h2, g_h2T_hi, g_h2T_lo, NO); }

// ---------------- agg1: mma.sync, A-fragments generated in registers ----------------
// block = (head, 128 i-rows, b); 8 warps as 4M x 2N; warp tile = 32 rows x 32 cols.
__global__ __launch_bounds__(256) void agg1_mma_kernel(const float* __restrict__ bh) {
    extern __shared__ __align__(16) char dsm[];
    __nv_bfloat16* sBhi = (__nv_bfloat16*)dsm;           // 64*72
    __nv_bfloat16* sBlo = sBhi + 64*72;
    float2* sef2 = (float2*)(sBlo + 64*72);              // 64

    const int tid = threadIdx.x, warp = tid >> 5, lane = tid & 31;
    const int head = blockIdx.x, i0 = blockIdx.y * 128, b = blockIdx.z;
    const int mi = warp >> 1, ni = warp & 1;
    const int iw = i0 + mi * 32;
    const uint32_t bhiA = smem_to_u32(sBhi), bloA = smem_to_u32(sBlo);
    const int rq = lane >> 2, cq = lane & 3;

    float2 u[2][2];
    u[0][0] = g_ef1[((size_t)b*NN + iw + rq)*NH + head];
    u[0][1] = g_ef1[((size_t)b*NN + iw + rq + 8)*NH + head];
    u[1][0] = g_ef1[((size_t)b*NN + iw + 16 + rq)*NH + head];
    u[1][1] = g_ef1[((size_t)b*NN + iw + 24 + rq)*NH + head];
    float lac[2][2] = {};
    float acc[2][2][2][4] = {};          // [mt][np][n8][frag]

    for (int jt = 0; jt < 32; ++jt) {
        const int j0 = jt * 64;
        __syncthreads();
        if (tid < 64) sef2[tid] = g_ef2[((size_t)b*NN + j0 + tid)*NH + head];
        #pragma unroll
        for (int rr = 0; rr < 2; ++rr) {
            int idx = tid + rr*256;
            int row = idx >> 3, ch = idx & 7;
            size_t so = ((size_t)(b*C1 + head*DD + row))*NN + j0 + ch*8;
            *(uint4*)(sBhi + row*72 + ch*8) = *(const uint4*)(g_h1T_hi + so);
            *(uint4*)(sBlo + row*72 + ch*8) = *(const uint4*)(g_h1T_lo + so);
        }
        __syncthreads();

        uint2 msk[2][2];
        #pragma unroll
        for (int mt = 0; mt < 2; ++mt) {
            msk[mt][0] = *(const uint2*)&g_adjp[((size_t)b*NN + iw + mt*16 + rq)*64 + (j0 >> 5)];
            msk[mt][1] = *(const uint2*)&g_adjp[((size_t)b*NN + iw + mt*16 + rq + 8)*64 + (j0 >> 5)];
        }

        #pragma unroll
        for (int ks = 0; ks < 4; ++ks) {
            const int jb = ks * 16;
            float4 va = *(const float4*)&sef2[jb + 2*cq];
            float4 vb = *(const float4*)&sef2[jb + 2*cq + 8];
            uint32_t ahi[2][4], alo[2][4];
            #pragma unroll
            for (int mt = 0; mt < 2; ++mt) {
                #pragma unroll
                for (int h = 0; h < 2; ++h) {
                    uint32_t mw = (ks < 2) ? msk[mt][h].x : msk[mt][h].y;
                    const int sh = (ks & 1)*16 + 2*cq;
                    const float2 uu = u[mt][h];
                    float w0 = ((mw >> sh) & 1u)     ? fmaxf(uu.x*va.x, uu.y*va.y) : 0.0f;
                    float w1 = ((mw >> (sh+1)) & 1u) ? fmaxf(uu.x*va.z, uu.y*va.w) : 0.0f;
                    float w2 = ((mw >> (sh+8)) & 1u) ? fmaxf(uu.x*vb.x, uu.y*vb.y) : 0.0f;
                    float w3 = ((mw >> (sh+9)) & 1u) ? fmaxf(uu.x*vb.z, uu.y*vb.w) : 0.0f;
                    lac[mt][h] += (w0 + w1) + (w2 + w3);
                    uint32_t hA, lA, hB, lB;
                    split_pair(w0, w1, hA, lA);
                    split_pair(w2, w3, hB, lB);
                    ahi[mt][h] = hA;  ahi[mt][h+2] = hB;
                    alo[mt][h] = lA;  alo[mt][h+2] = lB;
                }
            }
            #pragma unroll
            for (int np = 0; np < 2; ++np) {
                uint32_t boff = (uint32_t)(((ni*32 + np*16 + (lane & 15))*72 + jb + (lane >> 4)*8) * 2);
                uint32_t bh4[4], bl4[4];
                LDM_X4(bh4, bhiA + boff);
                LDM_X4(bl4, bloA + boff);
                #pragma unroll
                for (int mt = 0; mt < 2; ++mt) {
                    MMA_BF16(acc[mt][np][0], ahi[mt], bh4[0], bh4[2]);
                    MMA_BF16(acc[mt][np][1], ahi[mt], bh4[1], bh4[3]);
                    MMA_BF16(acc[mt][np][0], ahi[mt], bl4[0], bl4[2]);
                    MMA_BF16(acc[mt][np][1], ahi[mt], bl4[1], bl4[3]);
                    MMA_BF16(acc[mt][np][0], alo[mt], bh4[0], bh4[2]);
                    MMA_BF16(acc[mt][np][1], alo[mt], bh4[1], bh4[3]);
                }
            }
        }
    }
    #pragma unroll
    for (int mt = 0; mt < 2; ++mt)
        #pragma unroll
        for (int h = 0; h < 2; ++h) {
            lac[mt][h] += __shfl_xor_sync(0xFFFFFFFFu, lac[mt][h], 1);
            lac[mt][h] += __shfl_xor_sync(0xFFFFFFFFu, lac[mt][h], 2);
        }
    #pragma unroll
    for (int mt = 0; mt < 2; ++mt) {
        const float inv0 = 1.0f / lac[mt][0], inv1 = 1.0f / lac[mt][1];
        const int r0 = iw + mt*16 + rq, r1 = r0 + 8;
        #pragma unroll
        for (int np = 0; np < 2; ++np)
            #pragma unroll
            for (int n8 = 0; n8 < 2; ++n8) {
                const int c = ni*32 + np*16 + n8*8 + cq*2;
                const float bb0 = bh[head*DD + c], bb1 = bh[head*DD + c + 1];
                const float* a = acc[mt][np][n8];
                float z00 = a[0]*inv0 + bb0, z01 = a[1]*inv0 + bb1;
                float z10 = a[2]*inv1 + bb0, z11 = a[3]*inv1 + bb1;
                z00 = (z00 > 0.0f) ? z00 : expm1f(z00);
                z01 = (z01 > 0.0f) ? z01 : expm1f(z01);
                z10 = (z10 > 0.0f) ? z10 : expm1f(z10);
                z11 = (z11 > 0.0f) ? z11 : expm1f(z11);
                *(float2*)&g_z1[((size_t)b*NN + r0)*C1 + head*DD + c] = make_float2(z00, z01);
                *(float2*)&g_z1[((size_t)b*NN + r1)*C1 + head*DD + c] = make_float2(z10, z11);
            }
    }
}

// ---------------- agg2: mma.sync, N=128 ----------------
// block = (32 i-rows, b); 4 warps as 2M x 2N; warp tile = 16 rows x 64 cols.
__global__ __launch_bounds__(128) void agg2_mma_kernel(const float* __restrict__ bo,
                                                       float* __restrict__ out) {
    extern __shared__ __align__(16) char dsm[];
    __nv_bfloat16* sBhi = (__nv_bfloat16*)dsm;           // 128*72
    __nv_bfloat16* sBlo = sBhi + 128*72;
    float2* sef2 = (float2*)(sBlo + 128*72);             // 64

    const int tid = threadIdx.x, warp = tid >> 5, lane = tid & 31;
    const int i0 = blockIdx.x * 32, b = blockIdx.y;
    const int mi = warp >> 1, ni = warp & 1;
    const int iw = i0 + mi * 16;
    const uint32_t bhiA = smem_to_u32(sBhi), bloA = smem_to_u32(sBlo);
    const int rq = lane >> 2, cq = lane & 3;

    float2 u[2];
    u[0] = g_ef1o[(size_t)b*NN + iw + rq];
    u[1] = g_ef1o[(size_t)b*NN + iw + rq + 8];
    float lac[2] = {};
    float acc[4][2][4] = {};             // [np][n8][frag]

    for (int jt = 0; jt < 32; ++jt) {
        const int j0 = jt * 64;
        __syncthreads();
        if (tid < 64) sef2[tid] = g_ef2o[(size_t)b*NN + j0 + tid];
        #pragma unroll
        for (int rr = 0; rr < 8; ++rr) {
            int idx = tid + rr*128;
            int row = idx >> 3, ch = idx & 7;
            size_t so = ((size_t)(b*NO + row))*NN + j0 + ch*8;
            *(uint4*)(sBhi + row*72 + ch*8) = *(const uint4*)(g_h2T_hi + so);
            *(uint4*)(sBlo + row*72 + ch*8) = *(const uint4*)(g_h2T_lo + so);
        }
        __syncthreads();

        uint2 msk[2];
        msk[0] = *(const uint2*)&g_adjp[((size_t)b*NN + iw + rq)*64 + (j0 >> 5)];
        msk[1] = *(const uint2*)&g_adjp[((size_t)b*NN + iw + rq + 8)*64 + (j0 >> 5)];

        #pragma unroll
        for (int ks = 0; ks < 4; ++ks) {
            const int jb = ks * 16;
            float4 va = *(const float4*)&sef2[jb + 2*cq];
            float4 vb = *(const float4*)&sef2[jb + 2*cq + 8];
            uint32_t ahi[4], alo[4];
            #pragma unroll
            for (int h = 0; h < 2; ++h) {
                uint32_t mw = (ks < 2) ? msk[h].x : msk[h].y;
                const int sh = (ks & 1)*16 + 2*cq;
                const float2 uu = u[h];
                float w0 = ((mw >> sh) & 1u)     ? fmaxf(uu.x*va.x, uu.y*va.y) : 0.0f;
                float w1 = ((mw >> (sh+1)) & 1u) ? fmaxf(uu.x*va.z, uu.y*va.w) : 0.0f;
                float w2 = ((mw >> (sh+8)) & 1u) ? fmaxf(uu.x*vb.x, uu.y*vb.y) : 0.0f;
                float w3 = ((mw >> (sh+9)) & 1u) ? fmaxf(uu.x*vb.z, uu.y*vb.w) : 0.0f;
                lac[h] += (w0 + w1) + (w2 + w3);
                uint32_t hA, lA, hB, lB;
                split_pair(w0, w1, hA, lA);
                split_pair(w2, w3, hB, lB);
                ahi[h] = hA;  ahi[h+2] = hB;
                alo[h] = lA;  alo[h+2] = lB;
            }
            #pragma unroll
            for (int np = 0; np < 4; ++np) {
                uint32_t boff = (uint32_t)(((ni*64 + np*16 + (lane & 15))*72 + jb + (lane >> 4)*8) * 2);
                uint32_t bh4[4], bl4[4];
                LDM_X4(bh4, bhiA + boff);
                LDM_X4(bl4, bloA + boff);
                MMA_BF16(acc[np][0], ahi, bh4[0], bh4[2]);
                MMA_BF16(acc[np][1], ahi, bh4[1], bh4[3]);
                MMA_BF16(acc[np][0], ahi, bl4[0], bl4[2]);
                MMA_BF16(acc[np][1], ahi, bl4[1], bl4[3]);
                MMA_BF16(acc[np][0], alo, bh4[0], bh4[2]);
                MMA_BF16(acc[np][1], alo, bh4[1], bh4[3]);
            }
        }
    }
    #pragma unroll
    for (int h = 0; h < 2; ++h) {
        lac[h] += __shfl_xor_sync(0xFFFFFFFFu, lac[h], 1);
        lac[h] += __shfl_xor_sync(0xFFFFFFFFu, lac[h], 2);
    }
    const float inv0 = 1.0f / lac[0], inv1 = 1.0f / lac[1];
    const int r0 = iw + rq, r1 = r0 + 8;
    #pragma unroll
    for (int np = 0; np < 4; ++np)
        #pragma unroll
        for (int n8 = 0; n8 < 2; ++n8) {
            const int c = ni*64 + np*16 + n8*8 + cq*2;
            const float bb0 = bo[c], bb1 = bo[c + 1];
            const float* a = acc[np][n8];
            float z00 = fmaxf(a[0]*inv0 + bb0, 0.0f);
            float z01 = fmaxf(a[1]*inv0 + bb1, 0.0f);
            float z10 = fmaxf(a[2]*inv1 + bb0, 0.0f);
            float z11 = fmaxf(a[3]*inv1 + bb1, 0.0f);
            *(float2*)&out[((size_t)b*NN + r0)*NO + c] = make_float2(z00, z01);
            *(float2*)&out[((size_t)b*NN + r1)*NO + c] = make_float2(z10, z11);
        }
}

// ---------------------------------------------------------------------------
extern "C" void kernel_launch(void* const* d_in, const int* in_sizes, int n_in,
                              void* d_out, int out_size) {
    const float* x   = (const float*)d_in[0];
    const int*   adj = (const int*)  d_in[1];
    const float* Wh  = (const float*)d_in[2];
    const float* ah  = (const float*)d_in[3];
    const float* bh  = (const float*)d_in[4];
    const float* Wo  = (const float*)d_in[5];
    const float* ao  = (const float*)d_in[6];
    const float* bo  = (const float*)d_in[7];
    float* out = (float*)d_out;

    const int smem1 = 64*72*2*2 + 64*8;    // 18944
    const int smem2 = 128*72*2*2 + 64*8;   // 37376
    cudaFuncSetAttribute(agg1_mma_kernel, cudaFuncAttributeMaxDynamicSharedMemorySize, smem1);
    cudaFuncSetAttribute(agg2_mma_kernel, cudaFuncAttributeMaxDynamicSharedMemorySize, smem2);

    pack_adj_kernel<<<(BB*NN)/8, 256>>>(adj);
    gemm1_kernel<<<dim3(C1 / 64, (BB * NN) / 64), 256>>>(x, Wh);
    scores1_kernel<<<dim3(NN, BB), 256>>>(ah);
    trans1_kernel<<<dim3(NN / 32, C1 / 32, BB), 256>>>();
    agg1_mma_kernel<<<dim3(NH, NN / 128, BB), 256, smem1>>>(bh);
    gemm2_kernel<<<dim3(NO / 64, (BB * NN) / 64), 256>>>(Wo);
    scores2_kernel<<<dim3(NN, BB), 128>>>(ao);
    trans2_kernel<<<dim3(NN / 32, NO / 32, BB), 256>>>();
    agg2_mma_kernel<<<dim3(NN / 32, BB), 128, smem2>>>(bo, out);
}

// round 12
// speedup vs baseline: 3.0582x; 1.3273x over previous
#include <cuda_runtime.h>
#include <cuda_bf16.h>
#include <math.h>
#include <stdint.h>

#define BB 4
#define NN 2048
#define NF 256
#define NH 8
#define DD 64
#define C1 512
#define NO 128

__device__ float  g_h1[BB*NN*C1];
__device__ float  g_h2[BB*NN*NO];
__device__ float2 g_ef1[BB*NN*NH];
__device__ float2 g_ef2[BB*NN*NH];
__device__ float2 g_ef1o[BB*NN];
__device__ float2 g_ef2o[BB*NN];
__device__ __nv_bfloat16 g_h1T_hi[BB*C1*NN];
__device__ __nv_bfloat16 g_h1T_lo[BB*C1*NN];
__device__ __nv_bfloat16 g_h2T_hi[BB*NO*NN];
__device__ __nv_bfloat16 g_h2T_lo[BB*NO*NN];
__device__ uint32_t g_adjp[BB*NN*(NN/32)];
// GEMM operands (bf16 hi/lo split)
__device__ __nv_bfloat16 g_xh[BB*NN*NF],  g_xl[BB*NN*NF];
__device__ __nv_bfloat16 g_WhT_h[C1*NF],  g_WhT_l[C1*NF];     // [n=512][k=256]
__device__ __nv_bfloat16 g_WoT_h[NO*C1],  g_WoT_l[NO*C1];     // [n=128][k=512]
__device__ __nv_bfloat16 g_z1h[BB*NN*C1], g_z1l[BB*NN*C1];    // agg1 out / gemm2 A

// ---------------- helpers ----------------
__device__ __forceinline__ uint32_t smem_to_u32(const void* p) {
    uint32_t a;
    asm("{ .reg .u64 t; cvta.to.shared.u64 t, %1; cvt.u32.u64 %0, t; }" : "=r"(a) : "l"(p));
    return a;
}
#define LDM_X4(r, addr) \
    asm volatile("ldmatrix.sync.aligned.m8n8.x4.shared.b16 {%0,%1,%2,%3}, [%4];" \
        : "=r"((r)[0]), "=r"((r)[1]), "=r"((r)[2]), "=r"((r)[3]) : "r"(addr))
#define MMA_BF16(d, a, b0, b1) \
    asm volatile("mma.sync.aligned.m16n8k16.row.col.f32.bf16.bf16.f32 " \
        "{%0,%1,%2,%3}, {%4,%5,%6,%7}, {%8,%9}, {%0,%1,%2,%3};" \
        : "+f"((d)[0]), "+f"((d)[1]), "+f"((d)[2]), "+f"((d)[3]) \
        : "r"((a)[0]), "r"((a)[1]), "r"((a)[2]), "r"((a)[3]), "r"(b0), "r"(b1))

__device__ __forceinline__ uint32_t pack_bf16(float e0, float e1) {
    uint32_t r;
    asm("cvt.rn.satfinite.bf16x2.f32 %0, %1, %2;" : "=r"(r) : "f"(e1), "f"(e0));
    return r;
}
__device__ __forceinline__ void split_pair(float w0, float w1, uint32_t& hi, uint32_t& lo) {
    hi = pack_bf16(w0, w1);
    float r0 = w0 - __uint_as_float(hi << 16);
    float r1 = w1 - __uint_as_float(hi & 0xFFFF0000u);
    lo = pack_bf16(r0, r1);
}

// ---------------- prep: adj pack, operand splits ----------------
__global__ __launch_bounds__(256) void pack_adj_kernel(const int* __restrict__ adj) {
    const int lane = threadIdx.x & 31, warp = threadIdx.x >> 5;
    const int row = blockIdx.x * 8 + warp;
    const size_t base = (size_t)row * NN;
    uint32_t w0 = 0, w1 = 0;
    #pragma unroll 8
    for (int g = 0; g < 64; ++g) {
        uint32_t bits = __ballot_sync(0xFFFFFFFFu, adj[base + g*32 + lane] > 0);
        if (g < 32) { if (lane == g) w0 = bits; }
        else        { if (lane == g - 32) w1 = bits; }
    }
    g_adjp[(size_t)row*64 + lane] = w0;
    g_adjp[(size_t)row*64 + 32 + lane] = w1;
}
__global__ __launch_bounds__(256) void split_x_kernel(const float* __restrict__ x) {
    size_t i = (size_t)blockIdx.x * 256 + threadIdx.x;   // pair index
    float2 v = ((const float2*)x)[i];
    uint32_t hi, lo; split_pair(v.x, v.y, hi, lo);
    ((uint32_t*)g_xh)[i] = hi;
    ((uint32_t*)g_xl)[i] = lo;
}
__global__ __launch_bounds__(128) void transWh_kernel(const float* __restrict__ Wh) {
    const int n = blockIdx.x, t = threadIdx.x;           // n < 512, t < 128
    const int h = n >> 6, o = n & 63;
    float a = Wh[(size_t)h*NF*DD + (size_t)(2*t)*DD + o];
    float b = Wh[(size_t)h*NF*DD + (size_t)(2*t+1)*DD + o];
    uint32_t hi, lo; split_pair(a, b, hi, lo);
    ((uint32_t*)g_WhT_h)[n*(NF/2) + t] = hi;
    ((uint32_t*)g_WhT_l)[n*(NF/2) + t] = lo;
}
__global__ __launch_bounds__(256) void transWo_kernel(const float* __restrict__ Wo) {
    const int n = blockIdx.x, t = threadIdx.x;           // n < 128, t < 256
    float a = Wo[(size_t)(2*t)*NO + n];
    float b = Wo[(size_t)(2*t+1)*NO + n];
    uint32_t hi, lo; split_pair(a, b, hi, lo);
    ((uint32_t*)g_WoT_h)[n*(C1/2) + t] = hi;
    ((uint32_t*)g_WoT_l)[n*(C1/2) + t] = lo;
}

// ---------------- GEMM via mma.sync (3-pass bf16 split) ----------------
// block = 64 m x 128 n, 8 warps (4M x 2N), warp = 16m x 64n.
__device__ __forceinline__ void gemm_mma_body(
    const __nv_bfloat16* __restrict__ Ah, const __nv_bfloat16* __restrict__ Al,
    const __nv_bfloat16* __restrict__ BTh, const __nv_bfloat16* __restrict__ BTl,
    float* __restrict__ Out, int K, int Ncols, int nkt, char* dsm) {
    __nv_bfloat16* sAh = (__nv_bfloat16*)dsm;            // 64*72
    __nv_bfloat16* sAl = sAh + 64*72;
    __nv_bfloat16* sBh = sAl + 64*72;                    // 128*72
    __nv_bfloat16* sBl = sBh + 128*72;
    const int tid = threadIdx.x, warp = tid >> 5, lane = tid & 31;
    const int mi = warp >> 1, ni = warp & 1;
    const int m0 = blockIdx.y * 64, n0 = blockIdx.x * 128;
    const uint32_t sAhA = smem_to_u32(sAh), sAlA = smem_to_u32(sAl);
    const uint32_t sBhA = smem_to_u32(sBh), sBlA = smem_to_u32(sBl);
    const int rq = lane >> 2, cq = lane & 3;

    float acc[4][2][4] = {};
    for (int kt = 0; kt < nkt; ++kt) {
        const int k0 = kt * 64;
        __syncthreads();
        #pragma unroll
        for (int rr = 0; rr < 2; ++rr) {
            int idx = tid + rr*256;
            int row = idx >> 3, ch = idx & 7;
            size_t so = (size_t)(m0 + row)*K + k0 + ch*8;
            *(uint4*)(sAh + row*72 + ch*8) = *(const uint4*)(Ah + so);
            *(uint4*)(sAl + row*72 + ch*8) = *(const uint4*)(Al + so);
        }
        #pragma unroll
        for (int rr = 0; rr < 4; ++rr) {
            int idx = tid + rr*256;
            int row = idx >> 3, ch = idx & 7;
            size_t so = (size_t)(n0 + row)*K + k0 + ch*8;
            *(uint4*)(sBh + row*72 + ch*8) = *(const uint4*)(BTh + so);
            *(uint4*)(sBl + row*72 + ch*8) = *(const uint4*)(BTl + so);
        }
        __syncthreads();
        #pragma unroll
        for (int ks = 0; ks < 4; ++ks) {
            const int jb = ks * 16;
            uint32_t ah4[4], al4[4];
            uint32_t aoff = (uint32_t)(((mi*16 + (lane & 15))*72 + jb + (lane >> 4)*8) * 2);
            LDM_X4(ah4, sAhA + aoff);
            LDM_X4(al4, sAlA + aoff);
            #pragma unroll
            for (int np = 0; np < 4; ++np) {
                uint32_t boff = (uint32_t)(((ni*64 + np*16 + (lane & 15))*72 + jb + (lane >> 4)*8) * 2);
                uint32_t bh4[4], bl4[4];
                LDM_X4(bh4, sBhA + boff);
                LDM_X4(bl4, sBlA + boff);
                MMA_BF16(acc[np][0], ah4, bh4[0], bh4[2]);
                MMA_BF16(acc[np][1], ah4, bh4[1], bh4[3]);
                MMA_BF16(acc[np][0], ah4, bl4[0], bl4[2]);
                MMA_BF16(acc[np][1], ah4, bl4[1], bl4[3]);
                MMA_BF16(acc[np][0], al4, bh4[0], bh4[2]);
                MMA_BF16(acc[np][1], al4, bh4[1], bh4[3]);
            }
        }
    }
    const int r0 = m0 + mi*16 + rq, r1 = r0 + 8;
    #pragma unroll
    for (int np = 0; np < 4; ++np)
        #pragma unroll
        for (int n8 = 0; n8 < 2; ++n8) {
            const int c = n0 + ni*64 + np*16 + n8*8 + cq*2;
            const float* a = acc[np][n8];
            *(float2*)&Out[(size_t)r0*Ncols + c] = make_float2(a[0], a[1]);
            *(float2*)&Out[(size_t)r1*Ncols + c] = make_float2(a[2], a[3]);
        }
}
__global__ __launch_bounds__(256) void gemm1_mma_kernel() {
    extern __shared__ __align__(16) char dsm[];
    gemm_mma_body(g_xh, g_xl, g_WhT_h, g_WhT_l, g_h1, NF, C1, NF/64, dsm);
}
__global__ __launch_bounds__(256) void gemm2_mma_kernel() {
    extern __shared__ __align__(16) char dsm[];
    gemm_mma_body(g_z1h, g_z1l, g_WoT_h, g_WoT_l, g_h2, C1, NO, C1/64, dsm);
}

// ---------------- scores ----------------
__global__ __launch_bounds__(256) void scores1_kernel(const float* __restrict__ ah) {
    const int n = blockIdx.x, b = blockIdx.y;
    const int w = threadIdx.x >> 5, lane = threadIdx.x & 31;
    const size_t row = (size_t)b * NN + n;
    const float* hrow = &g_h1[row * C1 + w * DD];
    float v0 = hrow[lane], v1 = hrow[lane + 32];
    const float* a = &ah[w * 2 * DD];
    float s1 = v0 * a[lane] + v1 * a[lane + 32];
    float s2 = v0 * a[DD + lane] + v1 * a[DD + lane + 32];
    #pragma unroll
    for (int s = 16; s; s >>= 1) {
        s1 += __shfl_down_sync(0xFFFFFFFFu, s1, s);
        s2 += __shfl_down_sync(0xFFFFFFFFu, s2, s);
    }
    if (lane == 0) {
        g_ef1[row * NH + w] = make_float2(expf(s1), expf(0.1f * s1));
        g_ef2[row * NH + w] = make_float2(expf(s2), expf(0.1f * s2));
    }
}
__global__ __launch_bounds__(128) void scores2_kernel(const float* __restrict__ ao) {
    __shared__ float s1s[128], s2s[128];
    const int n = blockIdx.x, b = blockIdx.y;
    const size_t row = (size_t)b * NN + n;
    const int t = threadIdx.x;
    float v = g_h2[row * NO + t];
    s1s[t] = v * ao[t];
    s2s[t] = v * ao[NO + t];
    __syncthreads();
    for (int s = 64; s; s >>= 1) {
        if (t < s) { s1s[t] += s1s[t + s]; s2s[t] += s2s[t + s]; }
        __syncthreads();
    }
    if (t == 0) {
        g_ef1o[row] = make_float2(expf(s1s[0]), expf(0.1f * s1s[0]));
        g_ef2o[row] = make_float2(expf(s2s[0]), expf(0.1f * s2s[0]));
    }
}

// ---------------- transpose + bf16 split ----------------
__device__ __forceinline__ void trans_split(const float* __restrict__ src,
                                            __nv_bfloat16* __restrict__ dhi,
                                            __nv_bfloat16* __restrict__ dlo, int C) {
    __shared__ float tsm[32][33];
    const int lane = threadIdx.x & 31, ty = threadIdx.x >> 5;
    const int n0 = blockIdx.x * 32, c0 = blockIdx.y * 32, b = blockIdx.z;
    #pragma unroll
    for (int r = 0; r < 4; ++r)
        tsm[ty + r*8][lane] = src[((size_t)b*NN + n0 + ty + r*8)*C + c0 + lane];
    __syncthreads();
    #pragma unroll
    for (int r = 0; r < 4; ++r) {
        float v = tsm[lane][ty + r*8];
        __nv_bfloat16 h = __float2bfloat16(v);
        __nv_bfloat16 lo = __float2bfloat16(v - __bfloat162float(h));
        size_t o = ((size_t)b*C + c0 + ty + r*8)*NN + n0 + lane;
        dhi[o] = h; dlo[o] = lo;
    }
}
__global__ __launch_bounds__(256) void trans1_kernel() { trans_split(g_h1, g_h1T_hi, g_h1T_lo, C1); }
__global__ __launch_bounds__(256) void trans2_kernel() { trans_split(g_h2, g_h2T_hi, g_h2T_lo, NO); }

// ---------------- agg1: mma.sync, 8M x 1N (no weight-gen duplication) ----------------
// block = (head, 128 i-rows, b); 8 warps; warp = 16 rows x 64 cols.
__global__ __launch_bounds__(256) void agg1_mma_kernel(const float* __restrict__ bh) {
    extern __shared__ __align__(16) char dsm[];
    __nv_bfloat16* sBhi = (__nv_bfloat16*)dsm;           // 64*72
    __nv_bfloat16* sBlo = sBhi + 64*72;
    float2* sef2 = (float2*)(sBlo + 64*72);              // 64

    const int tid = threadIdx.x, warp = tid >> 5, lane = tid & 31;
    const int head = blockIdx.x, i0 = blockIdx.y * 128, b = blockIdx.z;
    const int iw = i0 + warp * 16;
    const uint32_t bhiA = smem_to_u32(sBhi), bloA = smem_to_u32(sBlo);
    const int rq = lane >> 2, cq = lane & 3;

    float2 u[2];
    u[0] = g_ef1[((size_t)b*NN + iw + rq)*NH + head];
    u[1] = g_ef1[((size_t)b*NN + iw + rq + 8)*NH + head];
    float lac[2] = {};
    float acc[4][2][4] = {};             // [np][n8][frag]

    for (int jt = 0; jt < 32; ++jt) {
        const int j0 = jt * 64;
        __syncthreads();
        if (tid < 64) sef2[tid] = g_ef2[((size_t)b*NN + j0 + tid)*NH + head];
        #pragma unroll
        for (int rr = 0; rr < 2; ++rr) {
            int idx = tid + rr*256;
            int row = idx >> 3, ch = idx & 7;
            size_t so = ((size_t)(b*C1 + head*DD + row))*NN + j0 + ch*8;
            *(uint4*)(sBhi + row*72 + ch*8) = *(const uint4*)(g_h1T_hi + so);
            *(uint4*)(sBlo + row*72 + ch*8) = *(const uint4*)(g_h1T_lo + so);
        }
        __syncthreads();

        uint2 msk[2];
        msk[0] = *(const uint2*)&g_adjp[((size_t)b*NN + iw + rq)*64 + (j0 >> 5)];
        msk[1] = *(const uint2*)&g_adjp[((size_t)b*NN + iw + rq + 8)*64 + (j0 >> 5)];

        #pragma unroll
        for (int ks = 0; ks < 4; ++ks) {
            const int jb = ks * 16;
            float4 va = *(const float4*)&sef2[jb + 2*cq];
            float4 vb = *(const float4*)&sef2[jb + 2*cq + 8];
            uint32_t ahi[4], alo[4];
            #pragma unroll
            for (int h = 0; h < 2; ++h) {
                uint32_t mw = (ks < 2) ? msk[h].x : msk[h].y;
                const int sh = (ks & 1)*16 + 2*cq;
                const float2 uu = u[h];
                float w0 = ((mw >> sh) & 1u)     ? fmaxf(uu.x*va.x, uu.y*va.y) : 0.0f;
                float w1 = ((mw >> (sh+1)) & 1u) ? fmaxf(uu.x*va.z, uu.y*va.w) : 0.0f;
                float w2 = ((mw >> (sh+8)) & 1u) ? fmaxf(uu.x*vb.x, uu.y*vb.y) : 0.0f;
                float w3 = ((mw >> (sh+9)) & 1u) ? fmaxf(uu.x*vb.z, uu.y*vb.w) : 0.0f;
                lac[h] += (w0 + w1) + (w2 + w3);
                uint32_t hA, lA, hB, lB;
                split_pair(w0, w1, hA, lA);
                split_pair(w2, w3, hB, lB);
                ahi[h] = hA;  ahi[h+2] = hB;
                alo[h] = lA;  alo[h+2] = lB;
            }
            #pragma unroll
            for (int np = 0; np < 4; ++np) {
                uint32_t boff = (uint32_t)(((np*16 + (lane & 15))*72 + jb + (lane >> 4)*8) * 2);
                uint32_t bh4[4], bl4[4];
                LDM_X4(bh4, bhiA + boff);
                LDM_X4(bl4, bloA + boff);
                MMA_BF16(acc[np][0], ahi, bh4[0], bh4[2]);
                MMA_BF16(acc[np][1], ahi, bh4[1], bh4[3]);
                MMA_BF16(acc[np][0], ahi, bl4[0], bl4[2]);
                MMA_BF16(acc[np][1], ahi, bl4[1], bl4[3]);
                MMA_BF16(acc[np][0], alo, bh4[0], bh4[2]);
                MMA_BF16(acc[np][1], alo, bh4[1], bh4[3]);
            }
        }
    }
    #pragma unroll
    for (int h = 0; h < 2; ++h) {
        lac[h] += __shfl_xor_sync(0xFFFFFFFFu, lac[h], 1);
        lac[h] += __shfl_xor_sync(0xFFFFFFFFu, lac[h], 2);
    }
    const float inv0 = 1.0f / lac[0], inv1 = 1.0f / lac[1];
    const int r0 = iw + rq, r1 = r0 + 8;
    #pragma unroll
    for (int np = 0; np < 4; ++np)
        #pragma unroll
        for (int n8 = 0; n8 < 2; ++n8) {
            const int c = np*16 + n8*8 + cq*2;
            const float bb0 = bh[head*DD + c], bb1 = bh[head*DD + c + 1];
            const float* a = acc[np][n8];
            float z00 = a[0]*inv0 + bb0, z01 = a[1]*inv0 + bb1;
            float z10 = a[2]*inv1 + bb0, z11 = a[3]*inv1 + bb1;
            z00 = (z00 > 0.0f) ? z00 : expm1f(z00);
            z01 = (z01 > 0.0f) ? z01 : expm1f(z01);
            z10 = (z10 > 0.0f) ? z10 : expm1f(z10);
            z11 = (z11 > 0.0f) ? z11 : expm1f(z11);
            uint32_t zh, zl;
            split_pair(z00, z01, zh, zl);
            *(uint32_t*)&g_z1h[((size_t)b*NN + r0)*C1 + head*DD + c] = zh;
            *(uint32_t*)&g_z1l[((size_t)b*NN + r0)*C1 + head*DD + c] = zl;
            split_pair(z10, z11, zh, zl);
            *(uint32_t*)&g_z1h[((size_t)b*NN + r1)*C1 + head*DD + c] = zh;
            *(uint32_t*)&g_z1l[((size_t)b*NN + r1)*C1 + head*DD + c] = zl;
        }
}

// ---------------- agg2: mma.sync, N=128 (unchanged layout) ----------------
__global__ __launch_bounds__(128) void agg2_mma_kernel(const float* __restrict__ bo,
                                                       float* __restrict__ out) {
    extern __shared__ __align__(16) char dsm[];
    __nv_bfloat16* sBhi = (__nv_bfloat16*)dsm;           // 128*72
    __nv_bfloat16* sBlo = sBhi + 128*72;
    float2* sef2 = (float2*)(sBlo + 128*72);             // 64

    const int tid = threadIdx.x, warp = tid >> 5, lane = tid & 31;
    const int i0 = blockIdx.x * 32, b = blockIdx.y;
    const int mi = warp >> 1, ni = warp & 1;
    const int iw = i0 + mi * 16;
    const uint32_t bhiA = smem_to_u32(sBhi), bloA = smem_to_u32(sBlo);
    const int rq = lane >> 2, cq = lane & 3;

    float2 u[2];
    u[0] = g_ef1o[(size_t)b*NN + iw + rq];
    u[1] = g_ef1o[(size_t)b*NN + iw + rq + 8];
    float lac[2] = {};
    float acc[4][2][4] = {};

    for (int jt = 0; jt < 32; ++jt) {
        const int j0 = jt * 64;
        __syncthreads();
        if (tid < 64) sef2[tid] = g_ef2o[(size_t)b*NN + j0 + tid];
        #pragma unroll
        for (int rr = 0; rr < 8; ++rr) {
            int idx = tid + rr*128;
            int row = idx >> 3, ch = idx & 7;
            size_t so = ((size_t)(b*NO + row))*NN + j0 + ch*8;
            *(uint4*)(sBhi + row*72 + ch*8) = *(const uint4*)(g_h2T_hi + so);
            *(uint4*)(sBlo + row*72 + ch*8) = *(const uint4*)(g_h2T_lo + so);
        }
        __syncthreads();

        uint2 msk[2];
        msk[0] = *(const uint2*)&g_adjp[((size_t)b*NN + iw + rq)*64 + (j0 >> 5)];
        msk[1] = *(const uint2*)&g_adjp[((size_t)b*NN + iw + rq + 8)*64 + (j0 >> 5)];

        #pragma unroll
        for (int ks = 0; ks < 4; ++ks) {
            const int jb = ks * 16;
            float4 va = *(const float4*)&sef2[jb + 2*cq];
            float4 vb = *(const float4*)&sef2[jb + 2*cq + 8];
            uint32_t ahi[4], alo[4];
            #pragma unroll
            for (int h = 0; h < 2; ++h) {
                uint32_t mw = (ks < 2) ? msk[h].x : msk[h].y;
                const int sh = (ks & 1)*16 + 2*cq;
                const float2 uu = u[h];
                float w0 = ((mw >> sh) & 1u)     ? fmaxf(uu.x*va.x, uu.y*va.y) : 0.0f;
                float w1 = ((mw >> (sh+1)) & 1u) ? fmaxf(uu.x*va.z, uu.y*va.w) : 0.0f;
                float w2 = ((mw >> (sh+8)) & 1u) ? fmaxf(uu.x*vb.x, uu.y*vb.y) : 0.0f;
                float w3 = ((mw >> (sh+9)) & 1u) ? fmaxf(uu.x*vb.z, uu.y*vb.w) : 0.0f;
                lac[h] += (w0 + w1) + (w2 + w3);
                uint32_t hA, lA, hB, lB;
                split_pair(w0, w1, hA, lA);
                split_pair(w2, w3, hB, lB);
                ahi[h] = hA;  ahi[h+2] = hB;
                alo[h] = lA;  alo[h+2] = lB;
            }
            #pragma unroll
            for (int np = 0; np < 4; ++np) {
                uint32_t boff = (uint32_t)(((ni*64 + np*16 + (lane & 15))*72 + jb + (lane >> 4)*8) * 2);
                uint32_t bh4[4], bl4[4];
                LDM_X4(bh4, bhiA + boff);
                LDM_X4(bl4, bloA + boff);
                MMA_BF16(acc[np][0], ahi, bh4[0], bh4[2]);
                MMA_BF16(acc[np][1], ahi, bh4[1], bh4[3]);
                MMA_BF16(acc[np][0], ahi, bl4[0], bl4[2]);
                MMA_BF16(acc[np][1], ahi, bl4[1], bl4[3]);
                MMA_BF16(acc[np][0], alo, bh4[0], bh4[2]);
                MMA_BF16(acc[np][1], alo, bh4[1], bh4[3]);
            }
        }
    }
    #pragma unroll
    for (int h = 0; h < 2; ++h) {
        lac[h] += __shfl_xor_sync(0xFFFFFFFFu, lac[h], 1);
        lac[h] += __shfl_xor_sync(0xFFFFFFFFu, lac[h], 2);
    }
    const float inv0 = 1.0f / lac[0], inv1 = 1.0f / lac[1];
    const int r0 = iw + rq, r1 = r0 + 8;
    #pragma unroll
    for (int np = 0; np < 4; ++np)
        #pragma unroll
        for (int n8 = 0; n8 < 2; ++n8) {
            const int c = ni*64 + np*16 + n8*8 + cq*2;
            const float bb0 = bo[c], bb1 = bo[c + 1];
            const float* a = acc[np][n8];
            float z00 = fmaxf(a[0]*inv0 + bb0, 0.0f);
            float z01 = fmaxf(a[1]*inv0 + bb1, 0.0f);
            float z10 = fmaxf(a[2]*inv1 + bb0, 0.0f);
            float z11 = fmaxf(a[3]*inv1 + bb1, 0.0f);
            *(float2*)&out[((size_t)b*NN + r0)*NO + c] = make_float2(z00, z01);
            *(float2*)&out[((size_t)b*NN + r1)*NO + c] = make_float2(z10, z11);
        }
}

// ---------------------------------------------------------------------------
extern "C" void kernel_launch(void* const* d_in, const int* in_sizes, int n_in,
                              void* d_out, int out_size) {
    const float* x   = (const float*)d_in[0];
    const int*   adj = (const int*)  d_in[1];
    const float* Wh  = (const float*)d_in[2];
    const float* ah  = (const float*)d_in[3];
    const float* bh  = (const float*)d_in[4];
    const float* Wo  = (const float*)d_in[5];
    const float* ao  = (const float*)d_in[6];
    const float* bo  = (const float*)d_in[7];
    float* out = (float*)d_out;

    const int smem_gemm = (64 + 64 + 128 + 128) * 72 * 2;   // 55296
    const int smem1 = 64*72*2*2 + 64*8;    // 18944
    const int smem2 = 128*72*2*2 + 64*8;   // 37376
    cudaFuncSetAttribute(gemm1_mma_kernel, cudaFuncAttributeMaxDynamicSharedMemorySize, smem_gemm);
    cudaFuncSetAttribute(gemm2_mma_kernel, cudaFuncAttributeMaxDynamicSharedMemorySize, smem_gemm);
    cudaFuncSetAttribute(agg1_mma_kernel, cudaFuncAttributeMaxDynamicSharedMemorySize, smem1);
    cudaFuncSetAttribute(agg2_mma_kernel, cudaFuncAttributeMaxDynamicSharedMemorySize, smem2);

    pack_adj_kernel<<<(BB*NN)/8, 256>>>(adj);
    split_x_kernel<<<(BB*NN*NF/2)/256, 256>>>(x);
    transWh_kernel<<<C1, 128>>>(Wh);
    transWo_kernel<<<NO, 256>>>(Wo);

    gemm1_mma_kernel<<<dim3(C1/128, (BB*NN)/64), 256, smem_gemm>>>();
    scores1_kernel<<<dim3(NN, BB), 256>>>(ah);
    trans1_kernel<<<dim3(NN / 32, C1 / 32, BB), 256>>>();
    agg1_mma_kernel<<<dim3(NH, NN / 128, BB), 256, smem1>>>(bh);

    gemm2_mma_kernel<<<dim3(NO/128, (BB*NN)/64), 256, smem_gemm>>>();
    scores2_kernel<<<dim3(NN, BB), 128>>>(ao);
    trans2_kernel<<<dim3(NN / 32, NO / 32, BB), 256>>>();
    agg2_mma_kernel<<<dim3(NN / 32, BB), 128, smem2>>>(bo, out);
}

// round 13
// speedup vs baseline: 3.5882x; 1.1733x over previous
#include <cuda_runtime.h>
#include <cuda_bf16.h>
#include <math.h>
#include <stdint.h>

#define BB 4
#define NN 2048
#define NF 256
#define NH 8
#define DD 64
#define C1 512
#define NO 128

__device__ float  g_h1[BB*NN*C1];
__device__ float  g_h2[BB*NN*NO];
__device__ float2 g_ef1[BB*NN*NH];
__device__ float2 g_ef2[BB*NN*NH];
__device__ float2 g_ef1o[BB*NN];
__device__ float2 g_ef2o[BB*NN];
__device__ __nv_bfloat16 g_h1T_hi[BB*C1*NN];
__device__ __nv_bfloat16 g_h1T_lo[BB*C1*NN];
__device__ __nv_bfloat16 g_h2T_hi[BB*NO*NN];
__device__ __nv_bfloat16 g_h2T_lo[BB*NO*NN];
__device__ uint32_t g_adjp[BB*NN*(NN/32)];
__device__ __nv_bfloat16 g_xh[BB*NN*NF],  g_xl[BB*NN*NF];
__device__ __nv_bfloat16 g_WhT_h[C1*NF],  g_WhT_l[C1*NF];
__device__ __nv_bfloat16 g_WoT_h[NO*C1],  g_WoT_l[NO*C1];
__device__ __nv_bfloat16 g_z1h[BB*NN*C1], g_z1l[BB*NN*C1];

// ---------------- helpers ----------------
__device__ __forceinline__ uint32_t smem_to_u32(const void* p) {
    uint32_t a;
    asm("{ .reg .u64 t; cvta.to.shared.u64 t, %1; cvt.u32.u64 %0, t; }" : "=r"(a) : "l"(p));
    return a;
}
#define LDM_X4(r, addr) \
    asm volatile("ldmatrix.sync.aligned.m8n8.x4.shared.b16 {%0,%1,%2,%3}, [%4];" \
        : "=r"((r)[0]), "=r"((r)[1]), "=r"((r)[2]), "=r"((r)[3]) : "r"(addr))
#define MMA_BF16(d, a, b0, b1) \
    asm volatile("mma.sync.aligned.m16n8k16.row.col.f32.bf16.bf16.f32 " \
        "{%0,%1,%2,%3}, {%4,%5,%6,%7}, {%8,%9}, {%0,%1,%2,%3};" \
        : "+f"((d)[0]), "+f"((d)[1]), "+f"((d)[2]), "+f"((d)[3]) \
        : "r"((a)[0]), "r"((a)[1]), "r"((a)[2]), "r"((a)[3]), "r"(b0), "r"(b1))

__device__ __forceinline__ uint32_t pack_bf16(float e0, float e1) {
    uint32_t r;
    asm("cvt.rn.satfinite.bf16x2.f32 %0, %1, %2;" : "=r"(r) : "f"(e1), "f"(e0));
    return r;
}
__device__ __forceinline__ void split_pair(float w0, float w1, uint32_t& hi, uint32_t& lo) {
    hi = pack_bf16(w0, w1);
    float r0 = w0 - __uint_as_float(hi << 16);
    float r1 = w1 - __uint_as_float(hi & 0xFFFF0000u);
    lo = pack_bf16(r0, r1);
}
// sum of the two bf16 halves of a packed pair (as fp32)
__device__ __forceinline__ float pair_sum(uint32_t p) {
    return __uint_as_float(p << 16) + __uint_as_float(p & 0xFFFF0000u);
}

// ---------------- prep ----------------
__global__ __launch_bounds__(256) void pack_adj_kernel(const int* __restrict__ adj) {
    const int lane = threadIdx.x & 31, warp = threadIdx.x >> 5;
    const int row = blockIdx.x * 8 + warp;
    const size_t base = (size_t)row * NN;
    uint32_t w0 = 0, w1 = 0;
    #pragma unroll 8
    for (int g = 0; g < 64; ++g) {
        uint32_t bits = __ballot_sync(0xFFFFFFFFu, adj[base + g*32 + lane] > 0);
        if (g < 32) { if (lane == g) w0 = bits; }
        else        { if (lane == g - 32) w1 = bits; }
    }
    g_adjp[(size_t)row*64 + lane] = w0;
    g_adjp[(size_t)row*64 + 32 + lane] = w1;
}
__global__ __launch_bounds__(256) void split_x_kernel(const float* __restrict__ x) {
    size_t i = (size_t)blockIdx.x * 256 + threadIdx.x;
    float2 v = ((const float2*)x)[i];
    uint32_t hi, lo; split_pair(v.x, v.y, hi, lo);
    ((uint32_t*)g_xh)[i] = hi;
    ((uint32_t*)g_xl)[i] = lo;
}
__global__ __launch_bounds__(128) void transWh_kernel(const float* __restrict__ Wh) {
    const int n = blockIdx.x, t = threadIdx.x;
    const int h = n >> 6, o = n & 63;
    float a = Wh[(size_t)h*NF*DD + (size_t)(2*t)*DD + o];
    float b = Wh[(size_t)h*NF*DD + (size_t)(2*t+1)*DD + o];
    uint32_t hi, lo; split_pair(a, b, hi, lo);
    ((uint32_t*)g_WhT_h)[n*(NF/2) + t] = hi;
    ((uint32_t*)g_WhT_l)[n*(NF/2) + t] = lo;
}
__global__ __launch_bounds__(256) void transWo_kernel(const float* __restrict__ Wo) {
    const int n = blockIdx.x, t = threadIdx.x;
    float a = Wo[(size_t)(2*t)*NO + n];
    float b = Wo[(size_t)(2*t+1)*NO + n];
    uint32_t hi, lo; split_pair(a, b, hi, lo);
    ((uint32_t*)g_WoT_h)[n*(C1/2) + t] = hi;
    ((uint32_t*)g_WoT_l)[n*(C1/2) + t] = lo;
}

// ---------------- GEMM via mma.sync (3-pass bf16 split) ----------------
__device__ __forceinline__ void gemm_mma_body(
    const __nv_bfloat16* __restrict__ Ah, const __nv_bfloat16* __restrict__ Al,
    const __nv_bfloat16* __restrict__ BTh, const __nv_bfloat16* __restrict__ BTl,
    float* __restrict__ Out, int K, int Ncols, int nkt, char* dsm) {
    __nv_bfloat16* sAh = (__nv_bfloat16*)dsm;
    __nv_bfloat16* sAl = sAh + 64*72;
    __nv_bfloat16* sBh = sAl + 64*72;
    __nv_bfloat16* sBl = sBh + 128*72;
    const int tid = threadIdx.x, warp = tid >> 5, lane = tid & 31;
    const int mi = warp >> 1, ni = warp & 1;
    const int m0 = blockIdx.y * 64, n0 = blockIdx.x * 128;
    const uint32_t sAhA = smem_to_u32(sAh), sAlA = smem_to_u32(sAl);
    const uint32_t sBhA = smem_to_u32(sBh), sBlA = smem_to_u32(sBl);
    const int rq = lane >> 2, cq = lane & 3;

    float acc[4][2][4] = {};
    for (int kt = 0; kt < nkt; ++kt) {
        const int k0 = kt * 64;
        __syncthreads();
        #pragma unroll
        for (int rr = 0; rr < 2; ++rr) {
            int idx = tid + rr*256;
            int row = idx >> 3, ch = idx & 7;
            size_t so = (size_t)(m0 + row)*K + k0 + ch*8;
            *(uint4*)(sAh + row*72 + ch*8) = *(const uint4*)(Ah + so);
            *(uint4*)(sAl + row*72 + ch*8) = *(const uint4*)(Al + so);
        }
        #pragma unroll
        for (int rr = 0; rr < 4; ++rr) {
            int idx = tid + rr*256;
            int row = idx >> 3, ch = idx & 7;
            size_t so = (size_t)(n0 + row)*K + k0 + ch*8;
            *(uint4*)(sBh + row*72 + ch*8) = *(const uint4*)(BTh + so);
            *(uint4*)(sBl + row*72 + ch*8) = *(const uint4*)(BTl + so);
        }
        __syncthreads();
        #pragma unroll
        for (int ks = 0; ks < 4; ++ks) {
            const int jb = ks * 16;
            uint32_t ah4[4], al4[4];
            uint32_t aoff = (uint32_t)(((mi*16 + (lane & 15))*72 + jb + (lane >> 4)*8) * 2);
            LDM_X4(ah4, sAhA + aoff);
            LDM_X4(al4, sAlA + aoff);
            #pragma unroll
            for (int np = 0; np < 4; ++np) {
                uint32_t boff = (uint32_t)(((ni*64 + np*16 + (lane & 15))*72 + jb + (lane >> 4)*8) * 2);
                uint32_t bh4[4], bl4[4];
                LDM_X4(bh4, sBhA + boff);
                LDM_X4(bl4, sBlA + boff);
                MMA_BF16(acc[np][0], ah4, bh4[0], bh4[2]);
                MMA_BF16(acc[np][1], ah4, bh4[1], bh4[3]);
                MMA_BF16(acc[np][0], ah4, bl4[0], bl4[2]);
                MMA_BF16(acc[np][1], ah4, bl4[1], bl4[3]);
                MMA_BF16(acc[np][0], al4, bh4[0], bh4[2]);
                MMA_BF16(acc[np][1], al4, bh4[1], bh4[3]);
            }
        }
    }
    const int r0 = m0 + mi*16 + rq, r1 = r0 + 8;
    #pragma unroll
    for (int np = 0; np < 4; ++np)
        #pragma unroll
        for (int n8 = 0; n8 < 2; ++n8) {
            const int c = n0 + ni*64 + np*16 + n8*8 + cq*2;
            const float* a = acc[np][n8];
            *(float2*)&Out[(size_t)r0*Ncols + c] = make_float2(a[0], a[1]);
            *(float2*)&Out[(size_t)r1*Ncols + c] = make_float2(a[2], a[3]);
        }
}
__global__ __launch_bounds__(256) void gemm1_mma_kernel() {
    extern __shared__ __align__(16) char dsm[];
    gemm_mma_body(g_xh, g_xl, g_WhT_h, g_WhT_l, g_h1, NF, C1, NF/64, dsm);
}
__global__ __launch_bounds__(256) void gemm2_mma_kernel() {
    extern __shared__ __align__(16) char dsm[];
    gemm_mma_body(g_z1h, g_z1l, g_WoT_h, g_WoT_l, g_h2, C1, NO, C1/64, dsm);
}

// ---------------- scores ----------------
__global__ __launch_bounds__(256) void scores1_kernel(const float* __restrict__ ah) {
    const int n = blockIdx.x, b = blockIdx.y;
    const int w = threadIdx.x >> 5, lane = threadIdx.x & 31;
    const size_t row = (size_t)b * NN + n;
    const float* hrow = &g_h1[row * C1 + w * DD];
    float v0 = hrow[lane], v1 = hrow[lane + 32];
    const float* a = &ah[w * 2 * DD];
    float s1 = v0 * a[lane] + v1 * a[lane + 32];
    float s2 = v0 * a[DD + lane] + v1 * a[DD + lane + 32];
    #pragma unroll
    for (int s = 16; s; s >>= 1) {
        s1 += __shfl_down_sync(0xFFFFFFFFu, s1, s);
        s2 += __shfl_down_sync(0xFFFFFFFFu, s2, s);
    }
    if (lane == 0) {
        g_ef1[row * NH + w] = make_float2(expf(s1), expf(0.1f * s1));
        g_ef2[row * NH + w] = make_float2(expf(s2), expf(0.1f * s2));
    }
}
__global__ __launch_bounds__(128) void scores2_kernel(const float* __restrict__ ao) {
    __shared__ float s1s[128], s2s[128];
    const int n = blockIdx.x, b = blockIdx.y;
    const size_t row = (size_t)b * NN + n;
    const int t = threadIdx.x;
    float v = g_h2[row * NO + t];
    s1s[t] = v * ao[t];
    s2s[t] = v * ao[NO + t];
    __syncthreads();
    for (int s = 64; s; s >>= 1) {
        if (t < s) { s1s[t] += s1s[t + s]; s2s[t] += s2s[t + s]; }
        __syncthreads();
    }
    if (t == 0) {
        g_ef1o[row] = make_float2(expf(s1s[0]), expf(0.1f * s1s[0]));
        g_ef2o[row] = make_float2(expf(s2s[0]), expf(0.1f * s2s[0]));
    }
}

// ---------------- transpose + bf16 split ----------------
__device__ __forceinline__ void trans_split(const float* __restrict__ src,
                                            __nv_bfloat16* __restrict__ dhi,
                                            __nv_bfloat16* __restrict__ dlo, int C) {
    __shared__ float tsm[32][33];
    const int lane = threadIdx.x & 31, ty = threadIdx.x >> 5;
    const int n0 = blockIdx.x * 32, c0 = blockIdx.y * 32, b = blockIdx.z;
    #pragma unroll
    for (int r = 0; r < 4; ++r)
        tsm[ty + r*8][lane] = src[((size_t)b*NN + n0 + ty + r*8)*C + c0 + lane];
    __syncthreads();
    #pragma unroll
    for (int r = 0; r < 4; ++r) {
        float v = tsm[lane][ty + r*8];
        __nv_bfloat16 h = __float2bfloat16(v);
        __nv_bfloat16 lo = __float2bfloat16(v - __bfloat162float(h));
        size_t o = ((size_t)b*C + c0 + ty + r*8)*NN + n0 + lane;
        dhi[o] = h; dlo[o] = lo;
    }
}
__global__ __launch_bounds__(256) void trans1_kernel() { trans_split(g_h1, g_h1T_hi, g_h1T_lo, C1); }
__global__ __launch_bounds__(256) void trans2_kernel() { trans_split(g_h2, g_h2T_hi, g_h2T_lo, NO); }

// ---------------- agg1: mma.sync, 8M x 1N, 2-pass (A in bf16, B hi/lo) ----------------
__global__ __launch_bounds__(256) void agg1_mma_kernel(const float* __restrict__ bh) {
    extern __shared__ __align__(16) char dsm[];
    __nv_bfloat16* sBhi = (__nv_bfloat16*)dsm;
    __nv_bfloat16* sBlo = sBhi + 64*72;
    float2* sef2 = (float2*)(sBlo + 64*72);

    const int tid = threadIdx.x, warp = tid >> 5, lane = tid & 31;
    const int head = blockIdx.x, i0 = blockIdx.y * 128, b = blockIdx.z;
    const int iw = i0 + warp * 16;
    const uint32_t bhiA = smem_to_u32(sBhi), bloA = smem_to_u32(sBlo);
    const int rq = lane >> 2, cq = lane & 3;

    float2 u[2];
    u[0] = g_ef1[((size_t)b*NN + iw + rq)*NH + head];
    u[1] = g_ef1[((size_t)b*NN + iw + rq + 8)*NH + head];
    float lac[2] = {};
    float acc[4][2][4] = {};

    for (int jt = 0; jt < 32; ++jt) {
        const int j0 = jt * 64;
        __syncthreads();
        if (tid < 64) sef2[tid] = g_ef2[((size_t)b*NN + j0 + tid)*NH + head];
        #pragma unroll
        for (int rr = 0; rr < 2; ++rr) {
            int idx = tid + rr*256;
            int row = idx >> 3, ch = idx & 7;
            size_t so = ((size_t)(b*C1 + head*DD + row))*NN + j0 + ch*8;
            *(uint4*)(sBhi + row*72 + ch*8) = *(const uint4*)(g_h1T_hi + so);
            *(uint4*)(sBlo + row*72 + ch*8) = *(const uint4*)(g_h1T_lo + so);
        }
        __syncthreads();

        uint2 msk[2];
        msk[0] = *(const uint2*)&g_adjp[((size_t)b*NN + iw + rq)*64 + (j0 >> 5)];
        msk[1] = *(const uint2*)&g_adjp[((size_t)b*NN + iw + rq + 8)*64 + (j0 >> 5)];

        #pragma unroll
        for (int ks = 0; ks < 4; ++ks) {
            const int jb = ks * 16;
            float4 va = *(const float4*)&sef2[jb + 2*cq];
            float4 vb = *(const float4*)&sef2[jb + 2*cq + 8];
            uint32_t ahi[4];
            #pragma unroll
            for (int h = 0; h < 2; ++h) {
                uint32_t mw = (ks < 2) ? msk[h].x : msk[h].y;
                const int sh = (ks & 1)*16 + 2*cq;
                const float2 uu = u[h];
                float w0 = ((mw >> sh) & 1u)     ? fmaxf(uu.x*va.x, uu.y*va.y) : 0.0f;
                float w1 = ((mw >> (sh+1)) & 1u) ? fmaxf(uu.x*va.z, uu.y*va.w) : 0.0f;
                float w2 = ((mw >> (sh+8)) & 1u) ? fmaxf(uu.x*vb.x, uu.y*vb.y) : 0.0f;
                float w3 = ((mw >> (sh+9)) & 1u) ? fmaxf(uu.x*vb.z, uu.y*vb.w) : 0.0f;
                uint32_t hA = pack_bf16(w0, w1);
                uint32_t hB = pack_bf16(w2, w3);
                lac[h] += pair_sum(hA) + pair_sum(hB);   // denominator = rounded weights
                ahi[h] = hA;  ahi[h+2] = hB;
            }
            #pragma unroll
            for (int np = 0; np < 4; ++np) {
                uint32_t boff = (uint32_t)(((np*16 + (lane & 15))*72 + jb + (lane >> 4)*8) * 2);
                uint32_t bh4[4], bl4[4];
                LDM_X4(bh4, bhiA + boff);
                LDM_X4(bl4, bloA + boff);
                MMA_BF16(acc[np][0], ahi, bh4[0], bh4[2]);
                MMA_BF16(acc[np][1], ahi, bh4[1], bh4[3]);
                MMA_BF16(acc[np][0], ahi, bl4[0], bl4[2]);
                MMA_BF16(acc[np][1], ahi, bl4[1], bl4[3]);
            }
        }
    }
    #pragma unroll
    for (int h = 0; h < 2; ++h) {
        lac[h] += __shfl_xor_sync(0xFFFFFFFFu, lac[h], 1);
        lac[h] += __shfl_xor_sync(0xFFFFFFFFu, lac[h], 2);
    }
    const float inv0 = 1.0f / lac[0], inv1 = 1.0f / lac[1];
    const int r0 = iw + rq, r1 = r0 + 8;
    #pragma unroll
    for (int np = 0; np < 4; ++np)
        #pragma unroll
        for (int n8 = 0; n8 < 2; ++n8) {
            const int c = np*16 + n8*8 + cq*2;
            const float bb0 = bh[head*DD + c], bb1 = bh[head*DD + c + 1];
            const float* a = acc[np][n8];
            float z00 = a[0]*inv0 + bb0, z01 = a[1]*inv0 + bb1;
            float z10 = a[2]*inv1 + bb0, z11 = a[3]*inv1 + bb1;
            z00 = (z00 > 0.0f) ? z00 : expm1f(z00);
            z01 = (z01 > 0.0f) ? z01 : expm1f(z01);
            z10 = (z10 > 0.0f) ? z10 : expm1f(z10);
            z11 = (z11 > 0.0f) ? z11 : expm1f(z11);
            uint32_t zh, zl;
            split_pair(z00, z01, zh, zl);
            *(uint32_t*)&g_z1h[((size_t)b*NN + r0)*C1 + head*DD + c] = zh;
            *(uint32_t*)&g_z1l[((size_t)b*NN + r0)*C1 + head*DD + c] = zl;
            split_pair(z10, z11, zh, zl);
            *(uint32_t*)&g_z1h[((size_t)b*NN + r1)*C1 + head*DD + c] = zh;
            *(uint32_t*)&g_z1l[((size_t)b*NN + r1)*C1 + head*DD + c] = zl;
        }
}

// ---------------- agg2: mma.sync, N=128, 2-pass ----------------
__global__ __launch_bounds__(128) void agg2_mma_kernel(const float* __restrict__ bo,
                                                       float* __restrict__ out) {
    extern __shared__ __align__(16) char dsm[];
    __nv_bfloat16* sBhi = (__nv_bfloat16*)dsm;
    __nv_bfloat16* sBlo = sBhi + 128*72;
    float2* sef2 = (float2*)(sBlo + 128*72);

    const int tid = threadIdx.x, warp = tid >> 5, lane = tid & 31;
    const int i0 = blockIdx.x * 32, b = blockIdx.y;
    const int mi = warp >> 1, ni = warp & 1;
    const int iw = i0 + mi * 16;
    const uint32_t bhiA = smem_to_u32(sBhi), bloA = smem_to_u32(sBlo);
    const int rq = lane >> 2, cq = lane & 3;

    float2 u[2];
    u[0] = g_ef1o[(size_t)b*NN + iw + rq];
    u[1] = g_ef1o[(size_t)b*NN + iw + rq + 8];
    float lac[2] = {};
    float acc[4][2][4] = {};

    for (int jt = 0; jt < 32; ++jt) {
        const int j0 = jt * 64;
        __syncthreads();
        if (tid < 64) sef2[tid] = g_ef2o[(size_t)b*NN + j0 + tid];
        #pragma unroll
        for (int rr = 0; rr < 8; ++rr) {
            int idx = tid + rr*128;
            int row = idx >> 3, ch = idx & 7;
            size_t so = ((size_t)(b*NO + row))*NN + j0 + ch*8;
            *(uint4*)(sBhi + row*72 + ch*8) = *(const uint4*)(g_h2T_hi + so);
            *(uint4*)(sBlo + row*72 + ch*8) = *(const uint4*)(g_h2T_lo + so);
        }
        __syncthreads();

        uint2 msk[2];
        msk[0] = *(const uint2*)&g_adjp[((size_t)b*NN + iw + rq)*64 + (j0 >> 5)];
        msk[1] = *(const uint2*)&g_adjp[((size_t)b*NN + iw + rq + 8)*64 + (j0 >> 5)];

        #pragma unroll
        for (int ks = 0; ks < 4; ++ks) {
            const int jb = ks * 16;
            float4 va = *(const float4*)&sef2[jb + 2*cq];
            float4 vb = *(const float4*)&sef2[jb + 2*cq + 8];
            uint32_t ahi[4];
            #pragma unroll
            for (int h = 0; h < 2; ++h) {
                uint32_t mw = (ks < 2) ? msk[h].x : msk[h].y;
                const int sh = (ks & 1)*16 + 2*cq;
                const float2 uu = u[h];
                float w0 = ((mw >> sh) & 1u)     ? fmaxf(uu.x*va.x, uu.y*va.y) : 0.0f;
                float w1 = ((mw >> (sh+1)) & 1u) ? fmaxf(uu.x*va.z, uu.y*va.w) : 0.0f;
                float w2 = ((mw >> (sh+8)) & 1u) ? fmaxf(uu.x*vb.x, uu.y*vb.y) : 0.0f;
                float w3 = ((mw >> (sh+9)) & 1u) ? fmaxf(uu.x*vb.z, uu.y*vb.w) : 0.0f;
                uint32_t hA = pack_bf16(w0, w1);
                uint32_t hB = pack_bf16(w2, w3);
                lac[h] += pair_sum(hA) + pair_sum(hB);
                ahi[h] = hA;  ahi[h+2] = hB;
            }
            #pragma unroll
            for (int np = 0; np < 4; ++np) {
                uint32_t boff = (uint32_t)(((ni*64 + np*16 + (lane & 15))*72 + jb + (lane >> 4)*8) * 2);
                uint32_t bh4[4], bl4[4];
                LDM_X4(bh4, bhiA + boff);
                LDM_X4(bl4, bloA + boff);
                MMA_BF16(acc[np][0], ahi, bh4[0], bh4[2]);
                MMA_BF16(acc[np][1], ahi, bh4[1], bh4[3]);
                MMA_BF16(acc[np][0], ahi, bl4[0], bl4[2]);
                MMA_BF16(acc[np][1], ahi, bl4[1], bl4[3]);
            }
        }
    }
    #pragma unroll
    for (int h = 0; h < 2; ++h) {
        lac[h] += __shfl_xor_sync(0xFFFFFFFFu, lac[h], 1);
        lac[h] += __shfl_xor_sync(0xFFFFFFFFu, lac[h], 2);
    }
    const float inv0 = 1.0f / lac[0], inv1 = 1.0f / lac[1];
    const int r0 = iw + rq, r1 = r0 + 8;
    #pragma unroll
    for (int np = 0; np < 4; ++np)
        #pragma unroll
        for (int n8 = 0; n8 < 2; ++n8) {
            const int c = ni*64 + np*16 + n8*8 + cq*2;
            const float bb0 = bo[c], bb1 = bo[c + 1];
            const float* a = acc[np][n8];
            float z00 = fmaxf(a[0]*inv0 + bb0, 0.0f);
            float z01 = fmaxf(a[1]*inv0 + bb1, 0.0f);
            float z10 = fmaxf(a[2]*inv1 + bb0, 0.0f);
            float z11 = fmaxf(a[3]*inv1 + bb1, 0.0f);
            *(float2*)&out[((size_t)b*NN + r0)*NO + c] = make_float2(z00, z01);
            *(float2*)&out[((size_t)b*NN + r1)*NO + c] = make_float2(z10, z11);
        }
}

// ---------------------------------------------------------------------------
extern "C" void kernel_launch(void* const* d_in, const int* in_sizes, int n_in,
                              void* d_out, int out_size) {
    const float* x   = (const float*)d_in[0];
    const int*   adj = (const int*)  d_in[1];
    const float* Wh  = (const float*)d_in[2];
    const float* ah  = (const float*)d_in[3];
    const float* bh  = (const float*)d_in[4];
    const float* Wo  = (const float*)d_in[5];
    const float* ao  = (const float*)d_in[6];
    const float* bo  = (const float*)d_in[7];
    float* out = (float*)d_out;

    const int smem_gemm = (64 + 64 + 128 + 128) * 72 * 2;   // 55296
    const int smem1 = 64*72*2*2 + 64*8;    // 18944
    const int smem2 = 128*72*2*2 + 64*8;   // 37376
    cudaFuncSetAttribute(gemm1_mma_kernel, cudaFuncAttributeMaxDynamicSharedMemorySize, smem_gemm);
    cudaFuncSetAttribute(gemm2_mma_kernel, cudaFuncAttributeMaxDynamicSharedMemorySize, smem_gemm);
    cudaFuncSetAttribute(agg1_mma_kernel, cudaFuncAttributeMaxDynamicSharedMemorySize, smem1);
    cudaFuncSetAttribute(agg2_mma_kernel, cudaFuncAttributeMaxDynamicSharedMemorySize, smem2);

    pack_adj_kernel<<<(BB*NN)/8, 256>>>(adj);
    split_x_kernel<<<(BB*NN*NF/2)/256, 256>>>(x);
    transWh_kernel<<<C1, 128>>>(Wh);
    transWo_kernel<<<NO, 256>>>(Wo);

    gemm1_mma_kernel<<<dim3(C1/128, (BB*NN)/64), 256, smem_gemm>>>();
    scores1_kernel<<<dim3(NN, BB), 256>>>(ah);
    trans1_kernel<<<dim3(NN / 32, C1 / 32, BB), 256>>>();
    agg1_mma_kernel<<<dim3(NH, NN / 128, BB), 256, smem1>>>(bh);

    gemm2_mma_kernel<<<dim3(NO/128, (BB*NN)/64), 256, smem_gemm>>>();
    scores2_kernel<<<dim3(NN, BB), 128>>>(ao);
    trans2_kernel<<<dim3(NN / 32, NO / 32, BB), 256>>>();
    agg2_mma_kernel<<<dim3(NN / 32, BB), 128, smem2>>>(bo, out);
}

// round 14
// speedup vs baseline: 4.6853x; 1.3058x over previous
#include <cuda_runtime.h>
#include <cuda_bf16.h>
#include <cuda_fp16.h>
#include <math.h>
#include <stdint.h>

#define BB 4
#define NN 2048
#define NF 256
#define NH 8
#define DD 64
#define C1 512
#define NO 128

__device__ float  g_h1[BB*NN*C1];
__device__ float  g_h2[BB*NN*NO];
__device__ float2 g_ef1[BB*NN*NH];
__device__ float2 g_ef2[BB*NN*NH];
__device__ float2 g_ef1o[BB*NN];
__device__ float2 g_ef2o[BB*NN];
__device__ __half g_h1T[BB*C1*NN];           // fp16 transposed h1
__device__ __half g_h2T[BB*NO*NN];           // fp16 transposed h2
__device__ uint32_t g_adjp[BB*NN*(NN/32)];
__device__ __nv_bfloat16 g_xh[BB*NN*NF],  g_xl[BB*NN*NF];
__device__ __nv_bfloat16 g_WhT_h[C1*NF],  g_WhT_l[C1*NF];
__device__ __nv_bfloat16 g_WoT_h[NO*C1],  g_WoT_l[NO*C1];
__device__ __nv_bfloat16 g_z1h[BB*NN*C1], g_z1l[BB*NN*C1];

// ---------------- helpers ----------------
__device__ __forceinline__ uint32_t smem_to_u32(const void* p) {
    uint32_t a;
    asm("{ .reg .u64 t; cvta.to.shared.u64 t, %1; cvt.u32.u64 %0, t; }" : "=r"(a) : "l"(p));
    return a;
}
#define LDM_X4(r, addr) \
    asm volatile("ldmatrix.sync.aligned.m8n8.x4.shared.b16 {%0,%1,%2,%3}, [%4];" \
        : "=r"((r)[0]), "=r"((r)[1]), "=r"((r)[2]), "=r"((r)[3]) : "r"(addr))
#define MMA_BF16(d, a, b0, b1) \
    asm volatile("mma.sync.aligned.m16n8k16.row.col.f32.bf16.bf16.f32 " \
        "{%0,%1,%2,%3}, {%4,%5,%6,%7}, {%8,%9}, {%0,%1,%2,%3};" \
        : "+f"((d)[0]), "+f"((d)[1]), "+f"((d)[2]), "+f"((d)[3]) \
        : "r"((a)[0]), "r"((a)[1]), "r"((a)[2]), "r"((a)[3]), "r"(b0), "r"(b1))
#define MMA_F16(d, a, b0, b1) \
    asm volatile("mma.sync.aligned.m16n8k16.row.col.f32.f16.f16.f32 " \
        "{%0,%1,%2,%3}, {%4,%5,%6,%7}, {%8,%9}, {%0,%1,%2,%3};" \
        : "+f"((d)[0]), "+f"((d)[1]), "+f"((d)[2]), "+f"((d)[3]) \
        : "r"((a)[0]), "r"((a)[1]), "r"((a)[2]), "r"((a)[3]), "r"(b0), "r"(b1))

__device__ __forceinline__ uint32_t pack_bf16(float e0, float e1) {
    uint32_t r;
    asm("cvt.rn.satfinite.bf16x2.f32 %0, %1, %2;" : "=r"(r) : "f"(e1), "f"(e0));
    return r;
}
__device__ __forceinline__ uint32_t pack_f16(float e0, float e1) {
    uint32_t r;
    asm("cvt.rn.f16x2.f32 %0, %1, %2;" : "=r"(r) : "f"(e1), "f"(e0));
    return r;
}
__device__ __forceinline__ void split_pair(float w0, float w1, uint32_t& hi, uint32_t& lo) {
    hi = pack_bf16(w0, w1);
    float r0 = w0 - __uint_as_float(hi << 16);
    float r1 = w1 - __uint_as_float(hi & 0xFFFF0000u);
    lo = pack_bf16(r0, r1);
}
// sum of the two fp16 halves of a packed pair (as fp32)
__device__ __forceinline__ float pair_sum_h(uint32_t p) {
    __half2 h = *reinterpret_cast<__half2*>(&p);
    float2 f = __half22float2(h);
    return f.x + f.y;
}

// ---------------- prep ----------------
__global__ __launch_bounds__(256) void pack_adj_kernel(const int* __restrict__ adj) {
    const int lane = threadIdx.x & 31, warp = threadIdx.x >> 5;
    const int row = blockIdx.x * 8 + warp;
    const size_t base = (size_t)row * NN;
    uint32_t w0 = 0, w1 = 0;
    #pragma unroll 8
    for (int g = 0; g < 64; ++g) {
        uint32_t bits = __ballot_sync(0xFFFFFFFFu, adj[base + g*32 + lane] > 0);
        if (g < 32) { if (lane == g) w0 = bits; }
        else        { if (lane == g - 32) w1 = bits; }
    }
    g_adjp[(size_t)row*64 + lane] = w0;
    g_adjp[(size_t)row*64 + 32 + lane] = w1;
}
__global__ __launch_bounds__(256) void split_x_kernel(const float* __restrict__ x) {
    size_t i = (size_t)blockIdx.x * 256 + threadIdx.x;
    float2 v = ((const float2*)x)[i];
    uint32_t hi, lo; split_pair(v.x, v.y, hi, lo);
    ((uint32_t*)g_xh)[i] = hi;
    ((uint32_t*)g_xl)[i] = lo;
}
__global__ __launch_bounds__(128) void transWh_kernel(const float* __restrict__ Wh) {
    const int n = blockIdx.x, t = threadIdx.x;
    const int h = n >> 6, o = n & 63;
    float a = Wh[(size_t)h*NF*DD + (size_t)(2*t)*DD + o];
    float b = Wh[(size_t)h*NF*DD + (size_t)(2*t+1)*DD + o];
    uint32_t hi, lo; split_pair(a, b, hi, lo);
    ((uint32_t*)g_WhT_h)[n*(NF/2) + t] = hi;
    ((uint32_t*)g_WhT_l)[n*(NF/2) + t] = lo;
}
__global__ __launch_bounds__(256) void transWo_kernel(const float* __restrict__ Wo) {
    const int n = blockIdx.x, t = threadIdx.x;
    float a = Wo[(size_t)(2*t)*NO + n];
    float b = Wo[(size_t)(2*t+1)*NO + n];
    uint32_t hi, lo; split_pair(a, b, hi, lo);
    ((uint32_t*)g_WoT_h)[n*(C1/2) + t] = hi;
    ((uint32_t*)g_WoT_l)[n*(C1/2) + t] = lo;
}

// ---------------- GEMM via mma.sync (3-pass bf16 split) ----------------
__device__ __forceinline__ void gemm_mma_body(
    const __nv_bfloat16* __restrict__ Ah, const __nv_bfloat16* __restrict__ Al,
    const __nv_bfloat16* __restrict__ BTh, const __nv_bfloat16* __restrict__ BTl,
    float* __restrict__ Out, int K, int Ncols, int nkt, char* dsm) {
    __nv_bfloat16* sAh = (__nv_bfloat16*)dsm;
    __nv_bfloat16* sAl = sAh + 64*72;
    __nv_bfloat16* sBh = sAl + 64*72;
    __nv_bfloat16* sBl = sBh + 128*72;
    const int tid = threadIdx.x, warp = tid >> 5, lane = tid & 31;
    const int mi = warp >> 1, ni = warp & 1;
    const int m0 = blockIdx.y * 64, n0 = blockIdx.x * 128;
    const uint32_t sAhA = smem_to_u32(sAh), sAlA = smem_to_u32(sAl);
    const uint32_t sBhA = smem_to_u32(sBh), sBlA = smem_to_u32(sBl);
    const int rq = lane >> 2, cq = lane & 3;

    float acc[4][2][4] = {};
    for (int kt = 0; kt < nkt; ++kt) {
        const int k0 = kt * 64;
        __syncthreads();
        #pragma unroll
        for (int rr = 0; rr < 2; ++rr) {
            int idx = tid + rr*256;
            int row = idx >> 3, ch = idx & 7;
            size_t so = (size_t)(m0 + row)*K + k0 + ch*8;
            *(uint4*)(sAh + row*72 + ch*8) = *(const uint4*)(Ah + so);
            *(uint4*)(sAl + row*72 + ch*8) = *(const uint4*)(Al + so);
        }
        #pragma unroll
        for (int rr = 0; rr < 4; ++rr) {
            int idx = tid + rr*256;
            int row = idx >> 3, ch = idx & 7;
            size_t so = (size_t)(n0 + row)*K + k0 + ch*8;
            *(uint4*)(sBh + row*72 + ch*8) = *(const uint4*)(BTh + so);
            *(uint4*)(sBl + row*72 + ch*8) = *(const uint4*)(BTl + so);
        }
        __syncthreads();
        #pragma unroll
        for (int ks = 0; ks < 4; ++ks) {
            const int jb = ks * 16;
            uint32_t ah4[4], al4[4];
            uint32_t aoff = (uint32_t)(((mi*16 + (lane & 15))*72 + jb + (lane >> 4)*8) * 2);
            LDM_X4(ah4, sAhA + aoff);
            LDM_X4(al4, sAlA + aoff);
            #pragma unroll
            for (int np = 0; np < 4; ++np) {
                uint32_t boff = (uint32_t)(((ni*64 + np*16 + (lane & 15))*72 + jb + (lane >> 4)*8) * 2);
                uint32_t bh4[4], bl4[4];
                LDM_X4(bh4, sBhA + boff);
                LDM_X4(bl4, sBlA + boff);
                MMA_BF16(acc[np][0], ah4, bh4[0], bh4[2]);
                MMA_BF16(acc[np][1], ah4, bh4[1], bh4[3]);
                MMA_BF16(acc[np][0], ah4, bl4[0], bl4[2]);
                MMA_BF16(acc[np][1], ah4, bl4[1], bl4[3]);
                MMA_BF16(acc[np][0], al4, bh4[0], bh4[2]);
                MMA_BF16(acc[np][1], al4, bh4[1], bh4[3]);
            }
        }
    }
    const int r0 = m0 + mi*16 + rq, r1 = r0 + 8;
    #pragma unroll
    for (int np = 0; np < 4; ++np)
        #pragma unroll
        for (int n8 = 0; n8 < 2; ++n8) {
            const int c = n0 + ni*64 + np*16 + n8*8 + cq*2;
            const float* a = acc[np][n8];
            *(float2*)&Out[(size_t)r0*Ncols + c] = make_float2(a[0], a[1]);
            *(float2*)&Out[(size_t)r1*Ncols + c] = make_float2(a[2], a[3]);
        }
}
__global__ __launch_bounds__(256) void gemm1_mma_kernel() {
    extern __shared__ __align__(16) char dsm[];
    gemm_mma_body(g_xh, g_xl, g_WhT_h, g_WhT_l, g_h1, NF, C1, NF/64, dsm);
}
__global__ __launch_bounds__(256) void gemm2_mma_kernel() {
    extern __shared__ __align__(16) char dsm[];
    gemm_mma_body(g_z1h, g_z1l, g_WoT_h, g_WoT_l, g_h2, C1, NO, C1/64, dsm);
}

// ---------------- scores ----------------
__global__ __launch_bounds__(256) void scores1_kernel(const float* __restrict__ ah) {
    const int n = blockIdx.x, b = blockIdx.y;
    const int w = threadIdx.x >> 5, lane = threadIdx.x & 31;
    const size_t row = (size_t)b * NN + n;
    const float* hrow = &g_h1[row * C1 + w * DD];
    float v0 = hrow[lane], v1 = hrow[lane + 32];
    const float* a = &ah[w * 2 * DD];
    float s1 = v0 * a[lane] + v1 * a[lane + 32];
    float s2 = v0 * a[DD + lane] + v1 * a[DD + lane + 32];
    #pragma unroll
    for (int s = 16; s; s >>= 1) {
        s1 += __shfl_down_sync(0xFFFFFFFFu, s1, s);
        s2 += __shfl_down_sync(0xFFFFFFFFu, s2, s);
    }
    if (lane == 0) {
        g_ef1[row * NH + w] = make_float2(expf(s1), expf(0.1f * s1));
        g_ef2[row * NH + w] = make_float2(expf(s2), expf(0.1f * s2));
    }
}
__global__ __launch_bounds__(128) void scores2_kernel(const float* __restrict__ ao) {
    __shared__ float s1s[128], s2s[128];
    const int n = blockIdx.x, b = blockIdx.y;
    const size_t row = (size_t)b * NN + n;
    const int t = threadIdx.x;
    float v = g_h2[row * NO + t];
    s1s[t] = v * ao[t];
    s2s[t] = v * ao[NO + t];
    __syncthreads();
    for (int s = 64; s; s >>= 1) {
        if (t < s) { s1s[t] += s1s[t + s]; s2s[t] += s2s[t + s]; }
        __syncthreads();
    }
    if (t == 0) {
        g_ef1o[row] = make_float2(expf(s1s[0]), expf(0.1f * s1s[0]));
        g_ef2o[row] = make_float2(expf(s2s[0]), expf(0.1f * s2s[0]));
    }
}

// ---------------- transpose -> fp16 ----------------
__device__ __forceinline__ void trans_f16(const float* __restrict__ src,
                                          __half* __restrict__ dst, int C) {
    __shared__ float tsm[32][33];
    const int lane = threadIdx.x & 31, ty = threadIdx.x >> 5;
    const int n0 = blockIdx.x * 32, c0 = blockIdx.y * 32, b = blockIdx.z;
    #pragma unroll
    for (int r = 0; r < 4; ++r)
        tsm[ty + r*8][lane] = src[((size_t)b*NN + n0 + ty + r*8)*C + c0 + lane];
    __syncthreads();
    #pragma unroll
    for (int r = 0; r < 4; ++r) {
        float v = tsm[lane][ty + r*8];
        dst[((size_t)b*C + c0 + ty + r*8)*NN + n0 + lane] = __float2half(v);
    }
}
__global__ __launch_bounds__(256) void trans1_kernel() { trans_f16(g_h1, g_h1T, C1); }
__global__ __launch_bounds__(256) void trans2_kernel() { trans_f16(g_h2, g_h2T, NO); }

// ---------------- agg1: fp16 single-pass mma.sync, 8M x 1N ----------------
__global__ __launch_bounds__(256) void agg1_mma_kernel(const float* __restrict__ bh) {
    extern __shared__ __align__(16) char dsm[];
    __half* sB = (__half*)dsm;                 // 64*72
    float2* sef2 = (float2*)(sB + 64*72);      // 64

    const int tid = threadIdx.x, warp = tid >> 5, lane = tid & 31;
    const int head = blockIdx.x, i0 = blockIdx.y * 128, b = blockIdx.z;
    const int iw = i0 + warp * 16;
    const uint32_t sBA = smem_to_u32(sB);
    const int rq = lane >> 2, cq = lane & 3;

    float2 u[2];
    u[0] = g_ef1[((size_t)b*NN + iw + rq)*NH + head];
    u[1] = g_ef1[((size_t)b*NN + iw + rq + 8)*NH + head];
    float lac[2] = {};
    float acc[4][2][4] = {};

    for (int jt = 0; jt < 32; ++jt) {
        const int j0 = jt * 64;
        __syncthreads();
        if (tid < 64) sef2[tid] = g_ef2[((size_t)b*NN + j0 + tid)*NH + head];
        #pragma unroll
        for (int rr = 0; rr < 2; ++rr) {
            int idx = tid + rr*256;
            int row = idx >> 3, ch = idx & 7;
            size_t so = ((size_t)(b*C1 + head*DD + row))*NN + j0 + ch*8;
            *(uint4*)(sB + row*72 + ch*8) = *(const uint4*)(g_h1T + so);
        }
        __syncthreads();

        uint2 msk[2];
        msk[0] = *(const uint2*)&g_adjp[((size_t)b*NN + iw + rq)*64 + (j0 >> 5)];
        msk[1] = *(const uint2*)&g_adjp[((size_t)b*NN + iw + rq + 8)*64 + (j0 >> 5)];

        #pragma unroll
        for (int ks = 0; ks < 4; ++ks) {
            const int jb = ks * 16;
            float4 va = *(const float4*)&sef2[jb + 2*cq];
            float4 vb = *(const float4*)&sef2[jb + 2*cq + 8];
            uint32_t ahi[4];
            #pragma unroll
            for (int h = 0; h < 2; ++h) {
                uint32_t mw = (ks < 2) ? msk[h].x : msk[h].y;
                const int sh = (ks & 1)*16 + 2*cq;
                const float2 uu = u[h];
                float w0 = ((mw >> sh) & 1u)     ? fmaxf(uu.x*va.x, uu.y*va.y) : 0.0f;
                float w1 = ((mw >> (sh+1)) & 1u) ? fmaxf(uu.x*va.z, uu.y*va.w) : 0.0f;
                float w2 = ((mw >> (sh+8)) & 1u) ? fmaxf(uu.x*vb.x, uu.y*vb.y) : 0.0f;
                float w3 = ((mw >> (sh+9)) & 1u) ? fmaxf(uu.x*vb.z, uu.y*vb.w) : 0.0f;
                uint32_t hA = pack_f16(w0, w1);
                uint32_t hB = pack_f16(w2, w3);
                lac[h] += pair_sum_h(hA) + pair_sum_h(hB);   // denominator = rounded weights
                ahi[h] = hA;  ahi[h+2] = hB;
            }
            #pragma unroll
            for (int np = 0; np < 4; ++np) {
                uint32_t boff = (uint32_t)(((np*16 + (lane & 15))*72 + jb + (lane >> 4)*8) * 2);
                uint32_t b4[4];
                LDM_X4(b4, sBA + boff);
                MMA_F16(acc[np][0], ahi, b4[0], b4[2]);
                MMA_F16(acc[np][1], ahi, b4[1], b4[3]);
            }
        }
    }
    #pragma unroll
    for (int h = 0; h < 2; ++h) {
        lac[h] += __shfl_xor_sync(0xFFFFFFFFu, lac[h], 1);
        lac[h] += __shfl_xor_sync(0xFFFFFFFFu, lac[h], 2);
    }
    const float inv0 = 1.0f / lac[0], inv1 = 1.0f / lac[1];
    const int r0 = iw + rq, r1 = r0 + 8;
    #pragma unroll
    for (int np = 0; np < 4; ++np)
        #pragma unroll
        for (int n8 = 0; n8 < 2; ++n8) {
            const int c = np*16 + n8*8 + cq*2;
            const float bb0 = bh[head*DD + c], bb1 = bh[head*DD + c + 1];
            const float* a = acc[np][n8];
            float z00 = a[0]*inv0 + bb0, z01 = a[1]*inv0 + bb1;
            float z10 = a[2]*inv1 + bb0, z11 = a[3]*inv1 + bb1;
            z00 = (z00 > 0.0f) ? z00 : expm1f(z00);
            z01 = (z01 > 0.0f) ? z01 : expm1f(z01);
            z10 = (z10 > 0.0f) ? z10 : expm1f(z10);
            z11 = (z11 > 0.0f) ? z11 : expm1f(z11);
            uint32_t zh, zl;
            split_pair(z00, z01, zh, zl);
            *(uint32_t*)&g_z1h[((size_t)b*NN + r0)*C1 + head*DD + c] = zh;
            *(uint32_t*)&g_z1l[((size_t)b*NN + r0)*C1 + head*DD + c] = zl;
            split_pair(z10, z11, zh, zl);
            *(uint32_t*)&g_z1h[((size_t)b*NN + r1)*C1 + head*DD + c] = zh;
            *(uint32_t*)&g_z1l[((size_t)b*NN + r1)*C1 + head*DD + c] = zl;
        }
}

// ---------------- agg2: fp16 single-pass mma.sync, N=128 ----------------
__global__ __launch_bounds__(128) void agg2_mma_kernel(const float* __restrict__ bo,
                                                       float* __restrict__ out) {
    extern __shared__ __align__(16) char dsm[];
    __half* sB = (__half*)dsm;                 // 128*72
    float2* sef2 = (float2*)(sB + 128*72);     // 64

    const int tid = threadIdx.x, warp = tid >> 5, lane = tid & 31;
    const int i0 = blockIdx.x * 32, b = blockIdx.y;
    const int mi = warp >> 1, ni = warp & 1;
    const int iw = i0 + mi * 16;
    const uint32_t sBA = smem_to_u32(sB);
    const int rq = lane >> 2, cq = lane & 3;

    float2 u[2];
    u[0] = g_ef1o[(size_t)b*NN + iw + rq];
    u[1] = g_ef1o[(size_t)b*NN + iw + rq + 8];
    float lac[2] = {};
    float acc[4][2][4] = {};

    for (int jt = 0; jt < 32; ++jt) {
        const int j0 = jt * 64;
        __syncthreads();
        if (tid < 64) sef2[tid] = g_ef2o[(size_t)b*NN + j0 + tid];
        #pragma unroll
        for (int rr = 0; rr < 8; ++rr) {
            int idx = tid + rr*128;
            int row = idx >> 3, ch = idx & 7;
            size_t so = ((size_t)(b*NO + row))*NN + j0 + ch*8;
            *(uint4*)(sB + row*72 + ch*8) = *(const uint4*)(g_h2T + so);
        }
        __syncthreads();

        uint2 msk[2];
        msk[0] = *(const uint2*)&g_adjp[((size_t)b*NN + iw + rq)*64 + (j0 >> 5)];
        msk[1] = *(const uint2*)&g_adjp[((size_t)b*NN + iw + rq + 8)*64 + (j0 >> 5)];

        #pragma unroll
        for (int ks = 0; ks < 4; ++ks) {
            const int jb = ks * 16;
            float4 va = *(const float4*)&sef2[jb + 2*cq];
            float4 vb = *(const float4*)&sef2[jb + 2*cq + 8];
            uint32_t ahi[4];
            #pragma unroll
            for (int h = 0; h < 2; ++h) {
                uint32_t mw = (ks < 2) ? msk[h].x : msk[h].y;
                const int sh = (ks & 1)*16 + 2*cq;
                const float2 uu = u[h];
                float w0 = ((mw >> sh) & 1u)     ? fmaxf(uu.x*va.x, uu.y*va.y) : 0.0f;
                float w1 = ((mw >> (sh+1)) & 1u) ? fmaxf(uu.x*va.z, uu.y*va.w) : 0.0f;
                float w2 = ((mw >> (sh+8)) & 1u) ? fmaxf(uu.x*vb.x, uu.y*vb.y) : 0.0f;
                float w3 = ((mw >> (sh+9)) & 1u) ? fmaxf(uu.x*vb.z, uu.y*vb.w) : 0.0f;
                uint32_t hA = pack_f16(w0, w1);
                uint32_t hB = pack_f16(w2, w3);
                lac[h] += pair_sum_h(hA) + pair_sum_h(hB);
                ahi[h] = hA;  ahi[h+2] = hB;
            }
            #pragma unroll
            for (int np = 0; np < 4; ++np) {
                uint32_t boff = (uint32_t)(((ni*64 + np*16 + (lane & 15))*72 + jb + (lane >> 4)*8) * 2);
                uint32_t b4[4];
                LDM_X4(b4, sBA + boff);
                MMA_F16(acc[np][0], ahi, b4[0], b4[2]);
                MMA_F16(acc[np][1], ahi, b4[1], b4[3]);
            }
        }
    }
    #pragma unroll
    for (int h = 0; h < 2; ++h) {
        lac[h] += __shfl_xor_sync(0xFFFFFFFFu, lac[h], 1);
        lac[h] += __shfl_xor_sync(0xFFFFFFFFu, lac[h], 2);
    }
    const float inv0 = 1.0f / lac[0], inv1 = 1.0f / lac[1];
    const int r0 = iw + rq, r1 = r0 + 8;
    #pragma unroll
    for (int np = 0; np < 4; ++np)
        #pragma unroll
        for (int n8 = 0; n8 < 2; ++n8) {
            const int c = ni*64 + np*16 + n8*8 + cq*2;
            const float bb0 = bo[c], bb1 = bo[c + 1];
            const float* a = acc[np][n8];
            float z00 = fmaxf(a[0]*inv0 + bb0, 0.0f);
            float z01 = fmaxf(a[1]*inv0 + bb1, 0.0f);
            float z10 = fmaxf(a[2]*inv1 + bb0, 0.0f);
            float z11 = fmaxf(a[3]*inv1 + bb1, 0.0f);
            *(float2*)&out[((size_t)b*NN + r0)*NO + c] = make_float2(z00, z01);
            *(float2*)&out[((size_t)b*NN + r1)*NO + c] = make_float2(z10, z11);
        }
}

// ---------------------------------------------------------------------------
extern "C" void kernel_launch(void* const* d_in, const int* in_sizes, int n_in,
                              void* d_out, int out_size) {
    const float* x   = (const float*)d_in[0];
    const int*   adj = (const int*)  d_in[1];
    const float* Wh  = (const float*)d_in[2];
    const float* ah  = (const float*)d_in[3];
    const float* bh  = (const float*)d_in[4];
    const float* Wo  = (const float*)d_in[5];
    const float* ao  = (const float*)d_in[6];
    const float* bo  = (const float*)d_in[7];
    float* out = (float*)d_out;

    const int smem_gemm = (64 + 64 + 128 + 128) * 72 * 2;   // 55296
    const int smem1 = 64*72*2 + 64*8;      // 9728
    const int smem2 = 128*72*2 + 64*8;     // 18944
    cudaFuncSetAttribute(gemm1_mma_kernel, cudaFuncAttributeMaxDynamicSharedMemorySize, smem_gemm);
    cudaFuncSetAttribute(gemm2_mma_kernel, cudaFuncAttributeMaxDynamicSharedMemorySize, smem_gemm);
    cudaFuncSetAttribute(agg1_mma_kernel, cudaFuncAttributeMaxDynamicSharedMemorySize, smem1);
    cudaFuncSetAttribute(agg2_mma_kernel, cudaFuncAttributeMaxDynamicSharedMemorySize, smem2);

    pack_adj_kernel<<<(BB*NN)/8, 256>>>(adj);
    split_x_kernel<<<(BB*NN*NF/2)/256, 256>>>(x);
    transWh_kernel<<<C1, 128>>>(Wh);
    transWo_kernel<<<NO, 256>>>(Wo);

    gemm1_mma_kernel<<<dim3(C1/128, (BB*NN)/64), 256, smem_gemm>>>();
    scores1_kernel<<<dim3(NN, BB), 256>>>(ah);
    trans1_kernel<<<dim3(NN / 32, C1 / 32, BB), 256>>>();
    agg1_mma_kernel<<<dim3(NH, NN / 128, BB), 256, smem1>>>(bh);

    gemm2_mma_kernel<<<dim3(NO/128, (BB*NN)/64), 256, smem_gemm>>>();
    scores2_kernel<<<dim3(NN, BB), 128>>>(ao);
    trans2_kernel<<<dim3(NN / 32, NO / 32, BB), 256>>>();
    agg2_mma_kernel<<<dim3(NN / 32, BB), 128, smem2>>>(bo, out);
}